// round 6
// baseline (speedup 1.0000x reference)
#include <cuda_runtime.h>
#include <cstdint>
#include <mma.h>
#include <math.h>

using namespace nvcuda;

#define SS 4096
#define CC 2048
#define HH 16
#define DD 128
#define EPSF 1.1920929e-07f

// Scratch (no cudaMalloc allowed)
__device__ float g_q[SS * CC];
__device__ float g_k[SS * CC];
__device__ float g_v[SS * CC];
__device__ float g_attn[SS * CC];

// ---------------------------------------------------------------------------
// helpers
// ---------------------------------------------------------------------------
__device__ __forceinline__ uint32_t f2tf32(float x) {
    uint32_t r;
    asm("cvt.rna.tf32.f32 %0, %1;\n" : "=r"(r) : "f"(x));
    return r;
}

__device__ __forceinline__ void mma8(float* c, const uint32_t* a,
                                     uint32_t b0, uint32_t b1) {
    asm volatile(
        "mma.sync.aligned.m16n8k8.row.col.f32.tf32.tf32.f32 "
        "{%0,%1,%2,%3}, {%4,%5,%6,%7}, {%8,%9}, {%0,%1,%2,%3};\n"
        : "+f"(c[0]), "+f"(c[1]), "+f"(c[2]), "+f"(c[3])
        : "r"(a[0]), "r"(a[1]), "r"(a[2]), "r"(a[3]), "r"(b0), "r"(b1));
}

// ---------------------------------------------------------------------------
// GEMM: Out[M,N] = A[M,K] @ B[N,K]^T + bias[N], optional fused RMSNorm+rope.
// 3xTF32 (hi/lo split) wmma, 128x128x32 tile, 256 threads = 8 warps (2x4).
// Register-prefetch pipelined: next K-tile gmem loads overlap current compute.
// If normw != nullptr: per-row RMSNorm over the 128-col block (== one head)
// followed by table rotary, fused in the epilogue (Q/K projections).
// ---------------------------------------------------------------------------
__global__ void __launch_bounds__(256)
gemm_nt_3xtf32(const float* __restrict__ A,
               const float* __restrict__ B,
               const float* __restrict__ bias,
               float* __restrict__ Out,
               const float* __restrict__ normw,
               const float* __restrict__ rope,
               int M, int N, int K)
{
    extern __shared__ float smem[];
    float* As_hi = smem;                  // [128][36]
    float* As_lo = smem + 128 * 36;
    float* Bs_hi = smem + 2 * 128 * 36;
    float* Bs_lo = smem + 3 * 128 * 36;

    const int t = threadIdx.x;
    const int warp = t >> 5;
    const int wr = warp >> 2;   // 0..1
    const int wc = warp & 3;    // 0..3
    const int m0 = blockIdx.y * 128;
    const int n0 = blockIdx.x * 128;

    // per-thread load coords: 4 rows (r stride 32), fixed c4
    const int lr = t >> 3;            // 0..31
    const int lc4 = (t & 7) * 4;      // 0,4,..28

    wmma::fragment<wmma::accumulator, 16, 16, 8, float> cfrag[4][2];
#pragma unroll
    for (int mi = 0; mi < 4; mi++)
#pragma unroll
        for (int nj = 0; nj < 2; nj++) wmma::fill_fragment(cfrag[mi][nj], 0.0f);

    float4 a_reg[4], b_reg[4];
#pragma unroll
    for (int i = 0; i < 4; i++) {
        int r = lr + i * 32;
        a_reg[i] = *(const float4*)&A[(size_t)(m0 + r) * K + lc4];
        b_reg[i] = *(const float4*)&B[(size_t)(n0 + r) * K + lc4];
    }

    for (int k0 = 0; k0 < K; k0 += 32) {
        // convert current regs -> smem hi/lo
#pragma unroll
        for (int i = 0; i < 4; i++) {
            int r = lr + i * 32;
            float4 av = a_reg[i], bv = b_reg[i];
            float4 ah, al, bh, bl;
            ah.x = __uint_as_float(f2tf32(av.x)); al.x = __uint_as_float(f2tf32(av.x - ah.x));
            ah.y = __uint_as_float(f2tf32(av.y)); al.y = __uint_as_float(f2tf32(av.y - ah.y));
            ah.z = __uint_as_float(f2tf32(av.z)); al.z = __uint_as_float(f2tf32(av.z - ah.z));
            ah.w = __uint_as_float(f2tf32(av.w)); al.w = __uint_as_float(f2tf32(av.w - ah.w));
            bh.x = __uint_as_float(f2tf32(bv.x)); bl.x = __uint_as_float(f2tf32(bv.x - bh.x));
            bh.y = __uint_as_float(f2tf32(bv.y)); bl.y = __uint_as_float(f2tf32(bv.y - bh.y));
            bh.z = __uint_as_float(f2tf32(bv.z)); bl.z = __uint_as_float(f2tf32(bv.z - bh.z));
            bh.w = __uint_as_float(f2tf32(bv.w)); bl.w = __uint_as_float(f2tf32(bv.w - bh.w));
            *(float4*)&As_hi[r * 36 + lc4] = ah;
            *(float4*)&As_lo[r * 36 + lc4] = al;
            *(float4*)&Bs_hi[r * 36 + lc4] = bh;
            *(float4*)&Bs_lo[r * 36 + lc4] = bl;
        }
        __syncthreads();

        // prefetch next K-tile (latency hidden behind compute below)
        if (k0 + 32 < K) {
#pragma unroll
            for (int i = 0; i < 4; i++) {
                int r = lr + i * 32;
                a_reg[i] = *(const float4*)&A[(size_t)(m0 + r) * K + k0 + 32 + lc4];
                b_reg[i] = *(const float4*)&B[(size_t)(n0 + r) * K + k0 + 32 + lc4];
            }
        }

#pragma unroll
        for (int ks = 0; ks < 4; ks++) {
            wmma::fragment<wmma::matrix_a, 16, 16, 8, wmma::precision::tf32,
                           wmma::row_major> ah[4], al[4];
            wmma::fragment<wmma::matrix_b, 16, 16, 8, wmma::precision::tf32,
                           wmma::col_major> bh[2], bl[2];
#pragma unroll
            for (int mi = 0; mi < 4; mi++) {
                wmma::load_matrix_sync(ah[mi], &As_hi[(wr * 64 + mi * 16) * 36 + ks * 8], 36);
                wmma::load_matrix_sync(al[mi], &As_lo[(wr * 64 + mi * 16) * 36 + ks * 8], 36);
            }
#pragma unroll
            for (int nj = 0; nj < 2; nj++) {
                wmma::load_matrix_sync(bh[nj], &Bs_hi[(wc * 32 + nj * 16) * 36 + ks * 8], 36);
                wmma::load_matrix_sync(bl[nj], &Bs_lo[(wc * 32 + nj * 16) * 36 + ks * 8], 36);
            }
#pragma unroll
            for (int mi = 0; mi < 4; mi++)
#pragma unroll
                for (int nj = 0; nj < 2; nj++) {
                    wmma::mma_sync(cfrag[mi][nj], al[mi], bh[nj], cfrag[mi][nj]);
                    wmma::mma_sync(cfrag[mi][nj], ah[mi], bl[nj], cfrag[mi][nj]);
                    wmma::mma_sync(cfrag[mi][nj], ah[mi], bh[nj], cfrag[mi][nj]);
                }
        }
        __syncthreads();
    }

    // epilogue: stage to smem (aliases tiles), add bias (+ optional norm+rope)
    float* Cs = smem;  // [128][132] = 67584 B <= 73728 B
#pragma unroll
    for (int mi = 0; mi < 4; mi++)
#pragma unroll
        for (int nj = 0; nj < 2; nj++)
            wmma::store_matrix_sync(&Cs[(wr * 64 + mi * 16) * 132 + wc * 32 + nj * 16],
                                    cfrag[mi][nj], 132, wmma::mem_row_major);
    __syncthreads();

    if (normw == nullptr) {
#pragma unroll
        for (int i = 0; i < 16; i++) {
            int idx = i * 256 + t;               // 0..4095
            int r = idx >> 5, c4 = (idx & 31) * 4;
            float4 cv = *(float4*)&Cs[r * 132 + c4];
            float4 bb = *(const float4*)&bias[n0 + c4];
            cv.x += bb.x; cv.y += bb.y; cv.z += bb.z; cv.w += bb.w;
            *(float4*)&Out[(size_t)(m0 + r) * N + n0 + c4] = cv;
        }
    } else {
        // fused RMSNorm (over this 128-col block == head dim) + rotary
        const int r = t >> 1, half = t & 1;
        const int s = m0 + r;
        float* row = &Cs[r * 132 + half * 64];
        const float* bias_h = &bias[n0 + half * 64];
        float ssq = 0.0f;
#pragma unroll
        for (int j = 0; j < 16; j++) {
            float4 c = ((float4*)row)[j];
            float4 bb = ((const float4*)bias_h)[j];
            c.x += bb.x; c.y += bb.y; c.z += bb.z; c.w += bb.w;
            ((float4*)row)[j] = c;
            ssq += c.x * c.x + c.y * c.y + c.z * c.z + c.w * c.w;
        }
        ssq += __shfl_xor_sync(0xffffffffu, ssq, 1);
        float inv = rsqrtf(ssq * (1.0f / 128.0f) + EPSF);
        const float* wv = &normw[half * 64];
        const float* rp = &rope[(size_t)s * 256 + half * 128];
        float* outp = &Out[(size_t)(m0 + r) * N + n0 + half * 64];
#pragma unroll
        for (int j = 0; j < 16; j++) {
            float4 c = ((float4*)row)[j];
            float4 ww = ((const float4*)wv)[j];
            float x0 = c.x * inv * ww.x;
            float x1 = c.y * inv * ww.y;
            float x2 = c.z * inv * ww.z;
            float x3 = c.w * inv * ww.w;
            float4 rA = ((const float4*)rp)[2 * j];      // pair p:   i0j0 i0j1 i1j0 i1j1
            float4 rB = ((const float4*)rp)[2 * j + 1];  // pair p+1
            float4 ov;
            ov.x = rA.x * x0 + rA.y * x1;
            ov.y = rA.z * x0 + rA.w * x1;
            ov.z = rB.x * x2 + rB.y * x3;
            ov.w = rB.z * x2 + rB.w * x3;
            ((float4*)outp)[j] = ov;
        }
    }
}

// ---------------------------------------------------------------------------
// Flash attention, online softmax in registers, register-prefetch pipelined.
// QK^T in 3xTF32 (Q hi in regs, Q lo / K hi / K lo in smem); PV in 1xTF32.
// Block: (128-query tile, head). 256 threads = 8 warps; warp owns 16 q rows.
// smem (tf32 bit words): Qlo[128][132] Ks_hi[64][132] Ks_lo[64][132]
//                        Vs[64][136] Ps[128][68]  -> 204800 B
// ---------------------------------------------------------------------------
__global__ void __launch_bounds__(256, 1)
flash_attn_tc(const float* __restrict__ q,
              const float* __restrict__ k,
              const float* __restrict__ v,
              float* __restrict__ o)
{
    extern __shared__ uint32_t usm[];
    uint32_t* Qlo  = usm;                    // [128][132]
    uint32_t* Ks_hi = Qlo + 128 * 132;       // [64][132]
    uint32_t* Ks_lo = Ks_hi + 64 * 132;      // [64][132]
    uint32_t* Vs    = Ks_lo + 64 * 132;      // [64][136]
    uint32_t* Ps    = Vs + 64 * 136;         // [128][68]

    const int h  = blockIdx.y;
    const int q0 = blockIdx.x * 128;
    const int t  = threadIdx.x;
    const int warp = t >> 5;
    const int lane = t & 31;
    const int g   = lane >> 2;   // 0..7
    const int tig = lane & 3;    // 0..3
    const int r0 = warp * 16 + g;      // local row (group 0), 0..127
    const int r1 = r0 + 8;             // local row (group 1)
    const float scale = 0.08838834764831845f;  // 1/sqrt(128)

    // per-thread kv-tile load coords: 8 rows (stride 32), fixed column c4
    const int lr = t >> 5;            // 0..7
    const int lc4 = (t & 31) * 4;     // 0..124

    // Q -> hi in registers, lo in smem (thread-private addressing)
    uint32_t qhi[16][4];
    {
        const float* qr0 = &q[((size_t)(q0 + r0) * HH + h) * DD];
        const float* qr1 = &q[((size_t)(q0 + r1) * HH + h) * DD];
#pragma unroll
        for (int ks = 0; ks < 16; ks++) {
            int c = ks * 8 + tig;
            float q00 = qr0[c] * scale;
            float q10 = qr1[c] * scale;
            float q01 = qr0[c + 4] * scale;
            float q11 = qr1[c + 4] * scale;
            qhi[ks][0] = f2tf32(q00);
            qhi[ks][1] = f2tf32(q10);
            qhi[ks][2] = f2tf32(q01);
            qhi[ks][3] = f2tf32(q11);
            Qlo[r0 * 132 + c]     = f2tf32(q00 - __uint_as_float(qhi[ks][0]));
            Qlo[r1 * 132 + c]     = f2tf32(q10 - __uint_as_float(qhi[ks][1]));
            Qlo[r0 * 132 + c + 4] = f2tf32(q01 - __uint_as_float(qhi[ks][2]));
            Qlo[r1 * 132 + c + 4] = f2tf32(q11 - __uint_as_float(qhi[ks][3]));
        }
    }

    float m0r = -1e30f, m1r = -1e30f, l0 = 0.0f, l1 = 0.0f;
    float oacc[16][4];
#pragma unroll
    for (int j = 0; j < 16; j++)
#pragma unroll
        for (int e = 0; e < 4; e++) oacc[j][e] = 0.0f;

    float4 pr[8];   // prefetch buffer (K and V lifetimes disjoint)

    // ---- prime tile 0
#pragma unroll
    for (int i = 0; i < 8; i++)
        pr[i] = *(const float4*)&k[((size_t)(0 + lr + i * 8) * HH + h) * DD + lc4];
#pragma unroll
    for (int i = 0; i < 8; i++) {
        int r = lr + i * 8;
        float4 kv4 = pr[i];
        uint4 kh, kl;
        kh.x = f2tf32(kv4.x); kl.x = f2tf32(kv4.x - __uint_as_float(kh.x));
        kh.y = f2tf32(kv4.y); kl.y = f2tf32(kv4.y - __uint_as_float(kh.y));
        kh.z = f2tf32(kv4.z); kl.z = f2tf32(kv4.z - __uint_as_float(kh.z));
        kh.w = f2tf32(kv4.w); kl.w = f2tf32(kv4.w - __uint_as_float(kh.w));
        *(uint4*)&Ks_hi[r * 132 + lc4] = kh;
        *(uint4*)&Ks_lo[r * 132 + lc4] = kl;
    }
#pragma unroll
    for (int i = 0; i < 8; i++)
        pr[i] = *(const float4*)&v[((size_t)(0 + lr + i * 8) * HH + h) * DD + lc4];
#pragma unroll
    for (int i = 0; i < 8; i++) {
        int r = lr + i * 8;
        float4 vv4 = pr[i];
        *(uint4*)&Vs[r * 136 + lc4] =
            make_uint4(f2tf32(vv4.x), f2tf32(vv4.y), f2tf32(vv4.z), f2tf32(vv4.w));
    }
    __syncthreads();

    for (int kv0 = 0; kv0 < SS; kv0 += 64) {
        const int nxt = kv0 + 64;
        const bool more = nxt < SS;

        // prefetch next K tile (overlaps QK compute)
        if (more) {
#pragma unroll
            for (int i = 0; i < 8; i++)
                pr[i] = *(const float4*)&k[((size_t)(nxt + lr + i * 8) * HH + h) * DD + lc4];
        }

        // scores: 16x64 per warp = 8 n-frags, k = 128 (16 ksteps), 3xTF32
        float sacc[8][4];
#pragma unroll
        for (int j = 0; j < 8; j++)
#pragma unroll
            for (int e = 0; e < 4; e++) sacc[j][e] = 0.0f;

#pragma unroll
        for (int ks = 0; ks < 16; ks++) {
            uint32_t aql[4];
            aql[0] = Qlo[r0 * 132 + ks * 8 + tig];
            aql[1] = Qlo[r1 * 132 + ks * 8 + tig];
            aql[2] = Qlo[r0 * 132 + ks * 8 + tig + 4];
            aql[3] = Qlo[r1 * 132 + ks * 8 + tig + 4];
#pragma unroll
            for (int j = 0; j < 8; j++) {
                uint32_t bh0 = Ks_hi[(j * 8 + g) * 132 + ks * 8 + tig];
                uint32_t bh1 = Ks_hi[(j * 8 + g) * 132 + ks * 8 + tig + 4];
                uint32_t bl0 = Ks_lo[(j * 8 + g) * 132 + ks * 8 + tig];
                uint32_t bl1 = Ks_lo[(j * 8 + g) * 132 + ks * 8 + tig + 4];
                mma8(sacc[j], aql,     bh0, bh1);   // lo*hi
                mma8(sacc[j], qhi[ks], bl0, bl1);   // hi*lo
                mma8(sacc[j], qhi[ks], bh0, bh1);   // hi*hi
            }
        }
        __syncthreads();           // Ks free

        // store next K tile (hi/lo) from prefetch regs
        if (more) {
#pragma unroll
            for (int i = 0; i < 8; i++) {
                int r = lr + i * 8;
                float4 kv4 = pr[i];
                uint4 kh, kl;
                kh.x = f2tf32(kv4.x); kl.x = f2tf32(kv4.x - __uint_as_float(kh.x));
                kh.y = f2tf32(kv4.y); kl.y = f2tf32(kv4.y - __uint_as_float(kh.y));
                kh.z = f2tf32(kv4.z); kl.z = f2tf32(kv4.z - __uint_as_float(kh.z));
                kh.w = f2tf32(kv4.w); kl.w = f2tf32(kv4.w - __uint_as_float(kh.w));
                *(uint4*)&Ks_hi[r * 132 + lc4] = kh;
                *(uint4*)&Ks_lo[r * 132 + lc4] = kl;
            }
            // prefetch next V tile (overlaps softmax + PV)
#pragma unroll
            for (int i = 0; i < 8; i++)
                pr[i] = *(const float4*)&v[((size_t)(nxt + lr + i * 8) * HH + h) * DD + lc4];
        }

        // online softmax (rows r0 and r1; quad = 4 lanes per row)
        float rmax0 = -1e30f, rmax1 = -1e30f;
#pragma unroll
        for (int j = 0; j < 8; j++) {
            rmax0 = fmaxf(rmax0, fmaxf(sacc[j][0], sacc[j][1]));
            rmax1 = fmaxf(rmax1, fmaxf(sacc[j][2], sacc[j][3]));
        }
#pragma unroll
        for (int off = 1; off < 4; off <<= 1) {
            rmax0 = fmaxf(rmax0, __shfl_xor_sync(0xffffffffu, rmax0, off));
            rmax1 = fmaxf(rmax1, __shfl_xor_sync(0xffffffffu, rmax1, off));
        }
        float mn0 = fmaxf(m0r, rmax0);
        float mn1 = fmaxf(m1r, rmax1);
        float cr0 = __expf(m0r - mn0);
        float cr1 = __expf(m1r - mn1);
        float rs0 = 0.0f, rs1 = 0.0f;
#pragma unroll
        for (int j = 0; j < 8; j++) {
            float e0 = __expf(sacc[j][0] - mn0);
            float e1 = __expf(sacc[j][1] - mn0);
            float e2 = __expf(sacc[j][2] - mn1);
            float e3 = __expf(sacc[j][3] - mn1);
            rs0 += e0 + e1;
            rs1 += e2 + e3;
            int col = j * 8 + 2 * tig;
            Ps[r0 * 68 + col]     = f2tf32(e0);
            Ps[r0 * 68 + col + 1] = f2tf32(e1);
            Ps[r1 * 68 + col]     = f2tf32(e2);
            Ps[r1 * 68 + col + 1] = f2tf32(e3);
        }
#pragma unroll
        for (int off = 1; off < 4; off <<= 1) {
            rs0 += __shfl_xor_sync(0xffffffffu, rs0, off);
            rs1 += __shfl_xor_sync(0xffffffffu, rs1, off);
        }
        l0 = l0 * cr0 + rs0;
        l1 = l1 * cr1 + rs1;
        m0r = mn0;
        m1r = mn1;
#pragma unroll
        for (int j = 0; j < 16; j++) {
            oacc[j][0] *= cr0; oacc[j][1] *= cr0;
            oacc[j][2] *= cr1; oacc[j][3] *= cr1;
        }
        __syncwarp();

        // O += P @ V : k = 64 (8 ksteps), n = 128 (16 frags), 1xTF32
#pragma unroll
        for (int kc = 0; kc < 8; kc++) {
            uint32_t a[4];
            a[0] = Ps[r0 * 68 + kc * 8 + tig];
            a[1] = Ps[r1 * 68 + kc * 8 + tig];
            a[2] = Ps[r0 * 68 + kc * 8 + tig + 4];
            a[3] = Ps[r1 * 68 + kc * 8 + tig + 4];
#pragma unroll
            for (int j = 0; j < 16; j++) {
                uint32_t b0 = Vs[(kc * 8 + tig) * 136 + j * 8 + g];
                uint32_t b1 = Vs[(kc * 8 + tig + 4) * 136 + j * 8 + g];
                mma8(oacc[j], a, b0, b1);
            }
        }
        __syncthreads();           // Vs free; Ks(next) visible

        if (more) {
#pragma unroll
            for (int i = 0; i < 8; i++) {
                int r = lr + i * 8;
                float4 vv4 = pr[i];
                *(uint4*)&Vs[r * 136 + lc4] =
                    make_uint4(f2tf32(vv4.x), f2tf32(vv4.y), f2tf32(vv4.z), f2tf32(vv4.w));
            }
            __syncthreads();       // Vs(next) visible
        }
    }

    // epilogue
    float inv0 = 1.0f / l0, inv1 = 1.0f / l1;
    float* o0 = &o[((size_t)(q0 + r0) * HH + h) * DD];
    float* o1 = &o[((size_t)(q0 + r1) * HH + h) * DD];
#pragma unroll
    for (int j = 0; j < 16; j++) {
        int col = j * 8 + 2 * tig;
        float2 s0 = make_float2(oacc[j][0] * inv0, oacc[j][1] * inv0);
        float2 s1 = make_float2(oacc[j][2] * inv1, oacc[j][3] * inv1);
        *(float2*)&o0[col] = s0;
        *(float2*)&o1[col] = s1;
    }
}

// ---------------------------------------------------------------------------
extern "C" void kernel_launch(void* const* d_in, const int* in_sizes, int n_in,
                              void* d_out, int out_size)
{
    const float* x    = (const float*)d_in[0];
    const float* rope = (const float*)d_in[1];
    const float* Wq   = (const float*)d_in[2];
    const float* bq   = (const float*)d_in[3];
    const float* Wk   = (const float*)d_in[4];
    const float* bk   = (const float*)d_in[5];
    const float* Wv   = (const float*)d_in[6];
    const float* bv   = (const float*)d_in[7];
    const float* qn_w = (const float*)d_in[8];
    const float* kn_w = (const float*)d_in[9];
    const float* Wo   = (const float*)d_in[10];
    const float* bo   = (const float*)d_in[11];
    float* out = (float*)d_out;

    float *qp, *kp, *vp, *ap;
    cudaGetSymbolAddress((void**)&qp, g_q);
    cudaGetSymbolAddress((void**)&kp, g_k);
    cudaGetSymbolAddress((void**)&vp, g_v);
    cudaGetSymbolAddress((void**)&ap, g_attn);

    const int smem_gemm = 4 * 128 * 36 * sizeof(float);              // 73728
    const int smem_attn = (128 * 132 + 2 * 64 * 132 + 64 * 136 + 128 * 68) * 4; // 204800
    cudaFuncSetAttribute(gemm_nt_3xtf32, cudaFuncAttributeMaxDynamicSharedMemorySize,
                         smem_gemm);
    cudaFuncSetAttribute(flash_attn_tc, cudaFuncAttributeMaxDynamicSharedMemorySize,
                         smem_attn);

    dim3 ggrid(CC / 128, SS / 128);
    gemm_nt_3xtf32<<<ggrid, 256, smem_gemm>>>(x, Wq, bq, qp, qn_w, rope, SS, CC, CC);
    gemm_nt_3xtf32<<<ggrid, 256, smem_gemm>>>(x, Wk, bk, kp, kn_w, rope, SS, CC, CC);
    gemm_nt_3xtf32<<<ggrid, 256, smem_gemm>>>(x, Wv, bv, vp, nullptr, nullptr, SS, CC, CC);

    dim3 agrid(SS / 128, HH);
    flash_attn_tc<<<agrid, 256, smem_attn>>>(qp, kp, vp, ap);

    gemm_nt_3xtf32<<<ggrid, 256, smem_gemm>>>(ap, Wo, bo, out, nullptr, nullptr, SS, CC, CC);
}

// round 7
// speedup vs baseline: 2.1969x; 2.1969x over previous
#include <cuda_runtime.h>
#include <cstdint>
#include <cuda_bf16.h>
#include <mma.h>
#include <math.h>

using namespace nvcuda;

#define SS 4096
#define CC 2048
#define HH 16
#define DD 128
#define EPSF 1.1920929e-07f

typedef __nv_bfloat16 bf16;

// Scratch (no cudaMalloc allowed)
__device__ float g_q[SS * CC];
__device__ float g_k[SS * CC];
__device__ float g_v[SS * CC];
__device__ float g_attn[SS * CC];

// ---------------------------------------------------------------------------
// helpers
// ---------------------------------------------------------------------------
__device__ __forceinline__ uint32_t f2tf32(float x) {
    uint32_t r;
    asm("cvt.rna.tf32.f32 %0, %1;\n" : "=r"(r) : "f"(x));
    return r;
}

// pack two floats as bf16x2 (x -> low half)
__device__ __forceinline__ uint32_t bfpack(float x, float y) {
    __nv_bfloat162 h = __floats2bfloat162_rn(x, y);
    return *(uint32_t*)&h;
}
// residual after bf16 rounding
__device__ __forceinline__ float bfres(float x) {
    return x - __bfloat162float(__float2bfloat16_rn(x));
}

// tf32 m16n8k8 (used for PV)
__device__ __forceinline__ void mma8(float* c, const uint32_t* a,
                                     uint32_t b0, uint32_t b1) {
    asm volatile(
        "mma.sync.aligned.m16n8k8.row.col.f32.tf32.tf32.f32 "
        "{%0,%1,%2,%3}, {%4,%5,%6,%7}, {%8,%9}, {%0,%1,%2,%3};\n"
        : "+f"(c[0]), "+f"(c[1]), "+f"(c[2]), "+f"(c[3])
        : "r"(a[0]), "r"(a[1]), "r"(a[2]), "r"(a[3]), "r"(b0), "r"(b1));
}

// bf16 m16n8k16 (used for QK)
__device__ __forceinline__ void mma16(float* c, const uint32_t* a,
                                      uint32_t b0, uint32_t b1) {
    asm volatile(
        "mma.sync.aligned.m16n8k16.row.col.f32.bf16.bf16.f32 "
        "{%0,%1,%2,%3}, {%4,%5,%6,%7}, {%8,%9}, {%0,%1,%2,%3};\n"
        : "+f"(c[0]), "+f"(c[1]), "+f"(c[2]), "+f"(c[3])
        : "r"(a[0]), "r"(a[1]), "r"(a[2]), "r"(a[3]), "r"(b0), "r"(b1));
}

// ---------------------------------------------------------------------------
// GEMM: Out[M,N] = A[M,K] @ B[N,K]^T + bias[N], optional fused RMSNorm+rope.
// bf16x3 (hi/lo split) wmma 16x16x16, 128x128x32 tile, 256 thr = 8 warps.
// Register-prefetch pipelined. If normw != nullptr: fused per-head
// RMSNorm + rotary in the epilogue (the 128-col block == one head).
// ---------------------------------------------------------------------------
__global__ void __launch_bounds__(256)
gemm_nt_bf16x3(const float* __restrict__ A,
               const float* __restrict__ B,
               const float* __restrict__ bias,
               float* __restrict__ Out,
               const float* __restrict__ normw,
               const float* __restrict__ rope,
               int M, int N, int K)
{
    extern __shared__ char smemc[];
    bf16* As_hi = (bf16*)smemc;          // [128][40]
    bf16* As_lo = As_hi + 128 * 40;
    bf16* Bs_hi = As_lo + 128 * 40;
    bf16* Bs_lo = Bs_hi + 128 * 40;

    const int t = threadIdx.x;
    const int warp = t >> 5;
    const int wr = warp >> 2;   // 0..1
    const int wc = warp & 3;    // 0..3
    const int m0 = blockIdx.y * 128;
    const int n0 = blockIdx.x * 128;

    const int lr = t >> 3;            // 0..31 (4 rows, stride 32)
    const int lc4 = (t & 7) * 4;      // 0,4,..28

    wmma::fragment<wmma::accumulator, 16, 16, 16, float> cfrag[4][2];
#pragma unroll
    for (int mi = 0; mi < 4; mi++)
#pragma unroll
        for (int nj = 0; nj < 2; nj++) wmma::fill_fragment(cfrag[mi][nj], 0.0f);

    float4 a_reg[4], b_reg[4];
#pragma unroll
    for (int i = 0; i < 4; i++) {
        int r = lr + i * 32;
        a_reg[i] = *(const float4*)&A[(size_t)(m0 + r) * K + lc4];
        b_reg[i] = *(const float4*)&B[(size_t)(n0 + r) * K + lc4];
    }

    for (int k0 = 0; k0 < K; k0 += 32) {
        // split current regs -> smem hi/lo (bf16)
#pragma unroll
        for (int i = 0; i < 4; i++) {
            int r = lr + i * 32;
            float4 av = a_reg[i], bv = b_reg[i];
            uint2 ah = make_uint2(bfpack(av.x, av.y), bfpack(av.z, av.w));
            uint2 al = make_uint2(bfpack(bfres(av.x), bfres(av.y)),
                                  bfpack(bfres(av.z), bfres(av.w)));
            uint2 bh = make_uint2(bfpack(bv.x, bv.y), bfpack(bv.z, bv.w));
            uint2 bl = make_uint2(bfpack(bfres(bv.x), bfres(bv.y)),
                                  bfpack(bfres(bv.z), bfres(bv.w)));
            *(uint2*)&As_hi[r * 40 + lc4] = ah;
            *(uint2*)&As_lo[r * 40 + lc4] = al;
            *(uint2*)&Bs_hi[r * 40 + lc4] = bh;
            *(uint2*)&Bs_lo[r * 40 + lc4] = bl;
        }
        __syncthreads();

        // prefetch next K-tile (latency hidden behind compute below)
        if (k0 + 32 < K) {
#pragma unroll
            for (int i = 0; i < 4; i++) {
                int r = lr + i * 32;
                a_reg[i] = *(const float4*)&A[(size_t)(m0 + r) * K + k0 + 32 + lc4];
                b_reg[i] = *(const float4*)&B[(size_t)(n0 + r) * K + k0 + 32 + lc4];
            }
        }

#pragma unroll
        for (int ks = 0; ks < 2; ks++) {
            wmma::fragment<wmma::matrix_a, 16, 16, 16, bf16, wmma::row_major> ah[4], al[4];
            wmma::fragment<wmma::matrix_b, 16, 16, 16, bf16, wmma::col_major> bh[2], bl[2];
#pragma unroll
            for (int mi = 0; mi < 4; mi++) {
                wmma::load_matrix_sync(ah[mi], &As_hi[(wr * 64 + mi * 16) * 40 + ks * 16], 40);
                wmma::load_matrix_sync(al[mi], &As_lo[(wr * 64 + mi * 16) * 40 + ks * 16], 40);
            }
#pragma unroll
            for (int nj = 0; nj < 2; nj++) {
                wmma::load_matrix_sync(bh[nj], &Bs_hi[(wc * 32 + nj * 16) * 40 + ks * 16], 40);
                wmma::load_matrix_sync(bl[nj], &Bs_lo[(wc * 32 + nj * 16) * 40 + ks * 16], 40);
            }
#pragma unroll
            for (int mi = 0; mi < 4; mi++)
#pragma unroll
                for (int nj = 0; nj < 2; nj++) {
                    wmma::mma_sync(cfrag[mi][nj], al[mi], bh[nj], cfrag[mi][nj]);
                    wmma::mma_sync(cfrag[mi][nj], ah[mi], bl[nj], cfrag[mi][nj]);
                    wmma::mma_sync(cfrag[mi][nj], ah[mi], bh[nj], cfrag[mi][nj]);
                }
        }
        __syncthreads();
    }

    // epilogue: stage to smem (aliases tiles), add bias (+ optional norm+rope)
    float* Cs = (float*)smemc;  // [128][132] = 67584 B
#pragma unroll
    for (int mi = 0; mi < 4; mi++)
#pragma unroll
        for (int nj = 0; nj < 2; nj++)
            wmma::store_matrix_sync(&Cs[(wr * 64 + mi * 16) * 132 + wc * 32 + nj * 16],
                                    cfrag[mi][nj], 132, wmma::mem_row_major);
    __syncthreads();

    if (normw == nullptr) {
#pragma unroll
        for (int i = 0; i < 16; i++) {
            int idx = i * 256 + t;               // 0..4095
            int r = idx >> 5, c4 = (idx & 31) * 4;
            float4 cv = *(float4*)&Cs[r * 132 + c4];
            float4 bb = *(const float4*)&bias[n0 + c4];
            cv.x += bb.x; cv.y += bb.y; cv.z += bb.z; cv.w += bb.w;
            *(float4*)&Out[(size_t)(m0 + r) * N + n0 + c4] = cv;
        }
    } else {
        // fused RMSNorm (over this 128-col block == head dim) + rotary
        const int r = t >> 1, half = t & 1;
        const int s = m0 + r;
        float* row = &Cs[r * 132 + half * 64];
        const float* bias_h = &bias[n0 + half * 64];
        float ssq = 0.0f;
#pragma unroll
        for (int j = 0; j < 16; j++) {
            float4 c = ((float4*)row)[j];
            float4 bb = ((const float4*)bias_h)[j];
            c.x += bb.x; c.y += bb.y; c.z += bb.z; c.w += bb.w;
            ((float4*)row)[j] = c;
            ssq += c.x * c.x + c.y * c.y + c.z * c.z + c.w * c.w;
        }
        ssq += __shfl_xor_sync(0xffffffffu, ssq, 1);
        float inv = rsqrtf(ssq * (1.0f / 128.0f) + EPSF);
        const float* wv = &normw[half * 64];
        const float* rp = &rope[(size_t)s * 256 + half * 128];
        float* outp = &Out[(size_t)(m0 + r) * N + n0 + half * 64];
#pragma unroll
        for (int j = 0; j < 16; j++) {
            float4 c = ((float4*)row)[j];
            float4 ww = ((const float4*)wv)[j];
            float x0 = c.x * inv * ww.x;
            float x1 = c.y * inv * ww.y;
            float x2 = c.z * inv * ww.z;
            float x3 = c.w * inv * ww.w;
            float4 rA = ((const float4*)rp)[2 * j];
            float4 rB = ((const float4*)rp)[2 * j + 1];
            float4 ov;
            ov.x = rA.x * x0 + rA.y * x1;
            ov.y = rA.z * x0 + rA.w * x1;
            ov.z = rB.x * x2 + rB.y * x3;
            ov.w = rB.z * x2 + rB.w * x3;
            ((float4*)outp)[j] = ov;
        }
    }
}

// ---------------------------------------------------------------------------
// Flash attention, online softmax in registers.
// QK^T in bf16x3 mma.m16n8k16 (Q hi+lo in regs, K hi/lo packed bf16x2 smem);
// PV in 1xTF32 m16n8k8.
// Block: (128-query tile, head). 256 threads = 8 warps; warp owns 16 q rows.
// smem (32-bit words): KsH[64][68] KsL[64][68] Vs[64][136] Ps[128][68]
//   -> 104448 B
// ---------------------------------------------------------------------------
__global__ void __launch_bounds__(256, 1)
flash_attn_tc(const float* __restrict__ q,
              const float* __restrict__ k,
              const float* __restrict__ v,
              float* __restrict__ o)
{
    extern __shared__ uint32_t usm[];
    uint32_t* KsH = usm;                 // [64][68]  bf16x2 words (hi)
    uint32_t* KsL = KsH + 64 * 68;       // [64][68]  bf16x2 words (lo)
    uint32_t* Vs  = KsL + 64 * 68;       // [64][136] tf32 words
    uint32_t* Ps  = Vs + 64 * 136;       // [128][68] tf32 words

    const int h  = blockIdx.y;
    const int q0 = blockIdx.x * 128;
    const int t  = threadIdx.x;
    const int warp = t >> 5;
    const int lane = t & 31;
    const int g   = lane >> 2;   // 0..7
    const int tig = lane & 3;    // 0..3
    const int r0 = warp * 16 + g;      // local row (group 0), 0..127
    const int r1 = r0 + 8;             // local row (group 1)
    const float scale = 0.08838834764831845f;  // 1/sqrt(128)

    // per-thread kv-tile load coords: 8 rows (stride 8), fixed column c4
    const int lr = t >> 5;            // 0..7
    const int lc4 = (t & 31) * 4;     // 0..124

    // Q -> bf16 hi+lo in registers, pre-scaled.
    // a-frag m16n8k16: a0=(r0, 2t..2t+1) a1=(r1, same) a2=(r0, 2t+8..9) a3=(r1, ..)
    uint32_t qh[8][4], ql[8][4];
    {
        const float* qr0 = &q[((size_t)(q0 + r0) * HH + h) * DD];
        const float* qr1 = &q[((size_t)(q0 + r1) * HH + h) * DD];
#pragma unroll
        for (int ks = 0; ks < 8; ks++) {
            int c = ks * 16 + 2 * tig;
            float a0 = qr0[c] * scale,     a1 = qr0[c + 1] * scale;
            float b0 = qr1[c] * scale,     b1 = qr1[c + 1] * scale;
            float c0 = qr0[c + 8] * scale, c1 = qr0[c + 9] * scale;
            float d0 = qr1[c + 8] * scale, d1 = qr1[c + 9] * scale;
            qh[ks][0] = bfpack(a0, a1);
            qh[ks][1] = bfpack(b0, b1);
            qh[ks][2] = bfpack(c0, c1);
            qh[ks][3] = bfpack(d0, d1);
            ql[ks][0] = bfpack(bfres(a0), bfres(a1));
            ql[ks][1] = bfpack(bfres(b0), bfres(b1));
            ql[ks][2] = bfpack(bfres(c0), bfres(c1));
            ql[ks][3] = bfpack(bfres(d0), bfres(d1));
        }
    }

    float m0r = -1e30f, m1r = -1e30f, l0 = 0.0f, l1 = 0.0f;
    float oacc[16][4];
#pragma unroll
    for (int j = 0; j < 16; j++)
#pragma unroll
        for (int e = 0; e < 4; e++) oacc[j][e] = 0.0f;

    for (int kv0 = 0; kv0 < SS; kv0 += 64) {
        __syncthreads();   // all warps done reading Ks/Vs/Ps from prev iter
        // fill K (bf16 hi/lo packed) and V (tf32) tiles
#pragma unroll
        for (int i = 0; i < 8; i++) {
            int r = lr + i * 8;
            size_t goff = ((size_t)(kv0 + r) * HH + h) * DD + lc4;
            float4 kv4 = *(const float4*)&k[goff];
            float4 vv4 = *(const float4*)&v[goff];
            uint2 kh = make_uint2(bfpack(kv4.x, kv4.y), bfpack(kv4.z, kv4.w));
            uint2 kl = make_uint2(bfpack(bfres(kv4.x), bfres(kv4.y)),
                                  bfpack(bfres(kv4.z), bfres(kv4.w)));
            *(uint2*)&KsH[r * 68 + (lc4 >> 1)] = kh;
            *(uint2*)&KsL[r * 68 + (lc4 >> 1)] = kl;
            *(uint4*)&Vs[r * 136 + lc4] =
                make_uint4(f2tf32(vv4.x), f2tf32(vv4.y), f2tf32(vv4.z), f2tf32(vv4.w));
        }
        __syncthreads();

        // scores: 16x64 per warp = 8 n-frags, k = 128 (8 k16-steps), bf16x3
        float sacc[8][4];
#pragma unroll
        for (int j = 0; j < 8; j++)
#pragma unroll
            for (int e = 0; e < 4; e++) sacc[j][e] = 0.0f;

#pragma unroll
        for (int ks = 0; ks < 8; ks++) {
#pragma unroll
            for (int j = 0; j < 8; j++) {
                int base = (j * 8 + g) * 68 + ks * 8 + tig;
                uint32_t bh0 = KsH[base], bh1 = KsH[base + 4];
                uint32_t bl0 = KsL[base], bl1 = KsL[base + 4];
                mma16(sacc[j], ql[ks], bh0, bh1);   // lo*hi
                mma16(sacc[j], qh[ks], bl0, bl1);   // hi*lo
                mma16(sacc[j], qh[ks], bh0, bh1);   // hi*hi
            }
        }

        // online softmax (rows r0 and r1; quad = 4 lanes per row)
        float rmax0 = -1e30f, rmax1 = -1e30f;
#pragma unroll
        for (int j = 0; j < 8; j++) {
            rmax0 = fmaxf(rmax0, fmaxf(sacc[j][0], sacc[j][1]));
            rmax1 = fmaxf(rmax1, fmaxf(sacc[j][2], sacc[j][3]));
        }
#pragma unroll
        for (int off = 1; off < 4; off <<= 1) {
            rmax0 = fmaxf(rmax0, __shfl_xor_sync(0xffffffffu, rmax0, off));
            rmax1 = fmaxf(rmax1, __shfl_xor_sync(0xffffffffu, rmax1, off));
        }
        float mn0 = fmaxf(m0r, rmax0);
        float mn1 = fmaxf(m1r, rmax1);
        float cr0 = __expf(m0r - mn0);
        float cr1 = __expf(m1r - mn1);
        float rs0 = 0.0f, rs1 = 0.0f;
#pragma unroll
        for (int j = 0; j < 8; j++) {
            float e0 = __expf(sacc[j][0] - mn0);
            float e1 = __expf(sacc[j][1] - mn0);
            float e2 = __expf(sacc[j][2] - mn1);
            float e3 = __expf(sacc[j][3] - mn1);
            rs0 += e0 + e1;
            rs1 += e2 + e3;
            int col = j * 8 + 2 * tig;
            Ps[r0 * 68 + col]     = f2tf32(e0);
            Ps[r0 * 68 + col + 1] = f2tf32(e1);
            Ps[r1 * 68 + col]     = f2tf32(e2);
            Ps[r1 * 68 + col + 1] = f2tf32(e3);
        }
#pragma unroll
        for (int off = 1; off < 4; off <<= 1) {
            rs0 += __shfl_xor_sync(0xffffffffu, rs0, off);
            rs1 += __shfl_xor_sync(0xffffffffu, rs1, off);
        }
        l0 = l0 * cr0 + rs0;
        l1 = l1 * cr1 + rs1;
        m0r = mn0;
        m1r = mn1;
#pragma unroll
        for (int j = 0; j < 16; j++) {
            oacc[j][0] *= cr0; oacc[j][1] *= cr0;
            oacc[j][2] *= cr1; oacc[j][3] *= cr1;
        }
        __syncwarp();   // Ps rows r0/r1 are warp-private (written+read by same warp)

        // O += P @ V : k = 64 (8 k8-steps), n = 128 (16 frags), 1xTF32
#pragma unroll
        for (int kc = 0; kc < 8; kc++) {
            uint32_t a[4];
            a[0] = Ps[r0 * 68 + kc * 8 + tig];
            a[1] = Ps[r1 * 68 + kc * 8 + tig];
            a[2] = Ps[r0 * 68 + kc * 8 + tig + 4];
            a[3] = Ps[r1 * 68 + kc * 8 + tig + 4];
#pragma unroll
            for (int j = 0; j < 16; j++) {
                uint32_t b0 = Vs[(kc * 8 + tig) * 136 + j * 8 + g];
                uint32_t b1 = Vs[(kc * 8 + tig + 4) * 136 + j * 8 + g];
                mma8(oacc[j], a, b0, b1);
            }
        }
    }

    // epilogue
    float inv0 = 1.0f / l0, inv1 = 1.0f / l1;
    float* o0 = &o[((size_t)(q0 + r0) * HH + h) * DD];
    float* o1 = &o[((size_t)(q0 + r1) * HH + h) * DD];
#pragma unroll
    for (int j = 0; j < 16; j++) {
        int col = j * 8 + 2 * tig;
        float2 s0 = make_float2(oacc[j][0] * inv0, oacc[j][1] * inv0);
        float2 s1 = make_float2(oacc[j][2] * inv1, oacc[j][3] * inv1);
        *(float2*)&o0[col] = s0;
        *(float2*)&o1[col] = s1;
    }
}

// ---------------------------------------------------------------------------
extern "C" void kernel_launch(void* const* d_in, const int* in_sizes, int n_in,
                              void* d_out, int out_size)
{
    const float* x    = (const float*)d_in[0];
    const float* rope = (const float*)d_in[1];
    const float* Wq   = (const float*)d_in[2];
    const float* bq   = (const float*)d_in[3];
    const float* Wk   = (const float*)d_in[4];
    const float* bk   = (const float*)d_in[5];
    const float* Wv   = (const float*)d_in[6];
    const float* bv   = (const float*)d_in[7];
    const float* qn_w = (const float*)d_in[8];
    const float* kn_w = (const float*)d_in[9];
    const float* Wo   = (const float*)d_in[10];
    const float* bo   = (const float*)d_in[11];
    float* out = (float*)d_out;

    float *qp, *kp, *vp, *ap;
    cudaGetSymbolAddress((void**)&qp, g_q);
    cudaGetSymbolAddress((void**)&kp, g_k);
    cudaGetSymbolAddress((void**)&vp, g_v);
    cudaGetSymbolAddress((void**)&ap, g_attn);

    const int smem_gemm = 128 * 132 * sizeof(float);   // 67584 (epilogue Cs is max)
    const int smem_attn = (2 * 64 * 68 + 64 * 136 + 128 * 68) * 4;  // 104448
    cudaFuncSetAttribute(gemm_nt_bf16x3, cudaFuncAttributeMaxDynamicSharedMemorySize,
                         smem_gemm);
    cudaFuncSetAttribute(flash_attn_tc, cudaFuncAttributeMaxDynamicSharedMemorySize,
                         smem_attn);

    dim3 ggrid(CC / 128, SS / 128);
    gemm_nt_bf16x3<<<ggrid, 256, smem_gemm>>>(x, Wq, bq, qp, qn_w, rope, SS, CC, CC);
    gemm_nt_bf16x3<<<ggrid, 256, smem_gemm>>>(x, Wk, bk, kp, kn_w, rope, SS, CC, CC);
    gemm_nt_bf16x3<<<ggrid, 256, smem_gemm>>>(x, Wv, bv, vp, nullptr, nullptr, SS, CC, CC);

    dim3 agrid(SS / 128, HH);
    flash_attn_tc<<<agrid, 256, smem_attn>>>(qp, kp, vp, ap);

    gemm_nt_bf16x3<<<ggrid, 256, smem_gemm>>>(ap, Wo, bo, out, nullptr, nullptr, SS, CC, CC);
}

// round 8
// speedup vs baseline: 2.3182x; 1.0552x over previous
#include <cuda_runtime.h>
#include <cstdint>
#include <cuda_bf16.h>
#include <mma.h>
#include <math.h>

using namespace nvcuda;

#define SS 4096
#define CC 2048
#define HH 16
#define DD 128
#define EPSF 1.1920929e-07f

typedef __nv_bfloat16 bf16;

// Scratch (no cudaMalloc allowed)
__device__ float    g_q[SS * CC];            // Q fp32 (post norm+rope)
__device__ uint32_t g_kh[SS * HH * 64];      // K hi, packed bf16x2 (d pairs)
__device__ uint32_t g_kl[SS * HH * 64];      // K lo, packed bf16x2
__device__ uint32_t g_v[SS * HH * 128];      // V tf32 words, d' = (d&7)*16+(d>>3)
__device__ float    g_attn[SS * CC];         // attention output fp32

// ---------------------------------------------------------------------------
// helpers
// ---------------------------------------------------------------------------
__device__ __forceinline__ uint32_t f2tf32(float x) {
    uint32_t r;
    asm("cvt.rna.tf32.f32 %0, %1;\n" : "=r"(r) : "f"(x));
    return r;
}
__device__ __forceinline__ uint32_t bfpack(float x, float y) {
    __nv_bfloat162 h = __floats2bfloat162_rn(x, y);
    return *(uint32_t*)&h;
}
__device__ __forceinline__ float bfres(float x) {
    return x - __bfloat162float(__float2bfloat16_rn(x));
}

// tf32 m16n8k8 (PV)
__device__ __forceinline__ void mma8(float* c, const uint32_t* a,
                                     uint32_t b0, uint32_t b1) {
    asm volatile(
        "mma.sync.aligned.m16n8k8.row.col.f32.tf32.tf32.f32 "
        "{%0,%1,%2,%3}, {%4,%5,%6,%7}, {%8,%9}, {%0,%1,%2,%3};\n"
        : "+f"(c[0]), "+f"(c[1]), "+f"(c[2]), "+f"(c[3])
        : "r"(a[0]), "r"(a[1]), "r"(a[2]), "r"(a[3]), "r"(b0), "r"(b1));
}
// bf16 m16n8k16 (QK)
__device__ __forceinline__ void mma16(float* c, const uint32_t* a,
                                      uint32_t b0, uint32_t b1) {
    asm volatile(
        "mma.sync.aligned.m16n8k16.row.col.f32.bf16.bf16.f32 "
        "{%0,%1,%2,%3}, {%4,%5,%6,%7}, {%8,%9}, {%0,%1,%2,%3};\n"
        : "+f"(c[0]), "+f"(c[1]), "+f"(c[2]), "+f"(c[3])
        : "r"(a[0]), "r"(a[1]), "r"(a[2]), "r"(a[3]), "r"(b0), "r"(b1));
}

#define CP16(dst_u32, src_ptr) \
    asm volatile("cp.async.cg.shared.global [%0], [%1], 16;" \
                 :: "r"(dst_u32), "l"(src_ptr) : "memory")
#define CP_COMMIT() asm volatile("cp.async.commit_group;" ::: "memory")

__device__ __forceinline__ void ldsm_x4(uint32_t addr, uint32_t& r0, uint32_t& r1,
                                        uint32_t& r2, uint32_t& r3) {
    asm volatile("ldmatrix.sync.aligned.m8n8.x4.shared.b16 {%0,%1,%2,%3}, [%4];"
                 : "=r"(r0), "=r"(r1), "=r"(r2), "=r"(r3) : "r"(addr));
}

// ---------------------------------------------------------------------------
// GEMM: Out[M,N] = A[M,K] @ B[N,K]^T + bias[N]; bf16x3 wmma 16x16x16,
// 128x128x32 tile, 256 thr = 8 warps. Register-prefetch pipelined.
// mode 0: plain fp32 out
// mode 1: fused RMSNorm+rope -> fp32 out (Q)
// mode 2: fused RMSNorm+rope -> packed bf16 hi/lo out (K)
// mode 3: plain -> tf32 d'-interleaved out (V)
// ---------------------------------------------------------------------------
__global__ void __launch_bounds__(256)
gemm_nt_bf16x3(const float* __restrict__ A,
               const float* __restrict__ B,
               const float* __restrict__ bias,
               float* __restrict__ Out,
               uint32_t* __restrict__ outW1,
               uint32_t* __restrict__ outW2,
               const float* __restrict__ normw,
               const float* __restrict__ rope,
               int mode, int M, int N, int K)
{
    extern __shared__ char smemc[];
    bf16* As_hi = (bf16*)smemc;          // [128][40]
    bf16* As_lo = As_hi + 128 * 40;
    bf16* Bs_hi = As_lo + 128 * 40;
    bf16* Bs_lo = Bs_hi + 128 * 40;

    const int t = threadIdx.x;
    const int warp = t >> 5;
    const int wr = warp >> 2;
    const int wc = warp & 3;
    const int m0 = blockIdx.y * 128;
    const int n0 = blockIdx.x * 128;
    const int hh = blockIdx.x;           // head index when N==2048

    const int lr = t >> 3;
    const int lc4 = (t & 7) * 4;

    wmma::fragment<wmma::accumulator, 16, 16, 16, float> cfrag[4][2];
#pragma unroll
    for (int mi = 0; mi < 4; mi++)
#pragma unroll
        for (int nj = 0; nj < 2; nj++) wmma::fill_fragment(cfrag[mi][nj], 0.0f);

    float4 a_reg[4], b_reg[4];
#pragma unroll
    for (int i = 0; i < 4; i++) {
        int r = lr + i * 32;
        a_reg[i] = *(const float4*)&A[(size_t)(m0 + r) * K + lc4];
        b_reg[i] = *(const float4*)&B[(size_t)(n0 + r) * K + lc4];
    }

    for (int k0 = 0; k0 < K; k0 += 32) {
#pragma unroll
        for (int i = 0; i < 4; i++) {
            int r = lr + i * 32;
            float4 av = a_reg[i], bv = b_reg[i];
            uint2 ah = make_uint2(bfpack(av.x, av.y), bfpack(av.z, av.w));
            uint2 al = make_uint2(bfpack(bfres(av.x), bfres(av.y)),
                                  bfpack(bfres(av.z), bfres(av.w)));
            uint2 bh = make_uint2(bfpack(bv.x, bv.y), bfpack(bv.z, bv.w));
            uint2 bl = make_uint2(bfpack(bfres(bv.x), bfres(bv.y)),
                                  bfpack(bfres(bv.z), bfres(bv.w)));
            *(uint2*)&As_hi[r * 40 + lc4] = ah;
            *(uint2*)&As_lo[r * 40 + lc4] = al;
            *(uint2*)&Bs_hi[r * 40 + lc4] = bh;
            *(uint2*)&Bs_lo[r * 40 + lc4] = bl;
        }
        __syncthreads();

        if (k0 + 32 < K) {
#pragma unroll
            for (int i = 0; i < 4; i++) {
                int r = lr + i * 32;
                a_reg[i] = *(const float4*)&A[(size_t)(m0 + r) * K + k0 + 32 + lc4];
                b_reg[i] = *(const float4*)&B[(size_t)(n0 + r) * K + k0 + 32 + lc4];
            }
        }

#pragma unroll
        for (int ks = 0; ks < 2; ks++) {
            wmma::fragment<wmma::matrix_a, 16, 16, 16, bf16, wmma::row_major> ah[4], al[4];
            wmma::fragment<wmma::matrix_b, 16, 16, 16, bf16, wmma::col_major> bh[2], bl[2];
#pragma unroll
            for (int mi = 0; mi < 4; mi++) {
                wmma::load_matrix_sync(ah[mi], &As_hi[(wr * 64 + mi * 16) * 40 + ks * 16], 40);
                wmma::load_matrix_sync(al[mi], &As_lo[(wr * 64 + mi * 16) * 40 + ks * 16], 40);
            }
#pragma unroll
            for (int nj = 0; nj < 2; nj++) {
                wmma::load_matrix_sync(bh[nj], &Bs_hi[(wc * 32 + nj * 16) * 40 + ks * 16], 40);
                wmma::load_matrix_sync(bl[nj], &Bs_lo[(wc * 32 + nj * 16) * 40 + ks * 16], 40);
            }
#pragma unroll
            for (int mi = 0; mi < 4; mi++)
#pragma unroll
                for (int nj = 0; nj < 2; nj++) {
                    wmma::mma_sync(cfrag[mi][nj], al[mi], bh[nj], cfrag[mi][nj]);
                    wmma::mma_sync(cfrag[mi][nj], ah[mi], bl[nj], cfrag[mi][nj]);
                    wmma::mma_sync(cfrag[mi][nj], ah[mi], bh[nj], cfrag[mi][nj]);
                }
        }
        __syncthreads();
    }

    // epilogue
    float* Cs = (float*)smemc;  // [128][132]
#pragma unroll
    for (int mi = 0; mi < 4; mi++)
#pragma unroll
        for (int nj = 0; nj < 2; nj++)
            wmma::store_matrix_sync(&Cs[(wr * 64 + mi * 16) * 132 + wc * 32 + nj * 16],
                                    cfrag[mi][nj], 132, wmma::mem_row_major);
    __syncthreads();

    if (mode == 0) {
#pragma unroll
        for (int i = 0; i < 16; i++) {
            int idx = i * 256 + t;
            int r = idx >> 5, c4 = (idx & 31) * 4;
            float4 cv = *(float4*)&Cs[r * 132 + c4];
            float4 bb = *(const float4*)&bias[n0 + c4];
            cv.x += bb.x; cv.y += bb.y; cv.z += bb.z; cv.w += bb.w;
            *(float4*)&Out[(size_t)(m0 + r) * N + n0 + c4] = cv;
        }
    } else if (mode == 3) {
        // V: tf32, d'-interleaved per (s, head)
#pragma unroll
        for (int i = 0; i < 16; i++) {
            int idx = i * 256 + t;
            int r = idx >> 5, c4 = (idx & 31) * 4;
            float4 cv = *(float4*)&Cs[r * 132 + c4];
            float4 bb = *(const float4*)&bias[n0 + c4];
            cv.x += bb.x; cv.y += bb.y; cv.z += bb.z; cv.w += bb.w;
            size_t base = ((size_t)(m0 + r) * HH + hh) * 128;
            float vals[4] = {cv.x, cv.y, cv.z, cv.w};
#pragma unroll
            for (int e = 0; e < 4; e++) {
                int d = c4 + e;
                int dp = (d & 7) * 16 + (d >> 3);
                outW1[base + dp] = f2tf32(vals[e]);
            }
        }
    } else {
        // fused RMSNorm (128-col block == one head) + rotary
        const int r = t >> 1, half = t & 1;
        const int s = m0 + r;
        float* row = &Cs[r * 132 + half * 64];
        const float* bias_h = &bias[n0 + half * 64];
        float ssq = 0.0f;
#pragma unroll
        for (int j = 0; j < 16; j++) {
            float4 c = ((float4*)row)[j];
            float4 bb = ((const float4*)bias_h)[j];
            c.x += bb.x; c.y += bb.y; c.z += bb.z; c.w += bb.w;
            ((float4*)row)[j] = c;
            ssq += c.x * c.x + c.y * c.y + c.z * c.z + c.w * c.w;
        }
        ssq += __shfl_xor_sync(0xffffffffu, ssq, 1);
        float inv = rsqrtf(ssq * (1.0f / 128.0f) + EPSF);
        const float* wv = &normw[half * 64];
        const float* rp = &rope[(size_t)s * 256 + half * 128];
        float* outp = &Out[(size_t)(m0 + r) * N + n0 + half * 64];
#pragma unroll
        for (int j = 0; j < 16; j++) {
            float4 c = ((float4*)row)[j];
            float4 ww = ((const float4*)wv)[j];
            float x0 = c.x * inv * ww.x;
            float x1 = c.y * inv * ww.y;
            float x2 = c.z * inv * ww.z;
            float x3 = c.w * inv * ww.w;
            float4 rA = ((const float4*)rp)[2 * j];
            float4 rB = ((const float4*)rp)[2 * j + 1];
            float4 ov;
            ov.x = rA.x * x0 + rA.y * x1;
            ov.y = rA.z * x0 + rA.w * x1;
            ov.z = rB.x * x2 + rB.y * x3;
            ov.w = rB.z * x2 + rB.w * x3;
            if (mode == 1) {
                ((float4*)outp)[j] = ov;
            } else {
                // mode 2: K packed bf16 hi/lo, word idx = d/2
                size_t kb = ((size_t)s * HH + hh) * 64 + half * 32 + j * 2;
                uint2 wh = make_uint2(bfpack(ov.x, ov.y), bfpack(ov.z, ov.w));
                uint2 wl = make_uint2(bfpack(bfres(ov.x), bfres(ov.y)),
                                      bfpack(bfres(ov.z), bfres(ov.w)));
                *(uint2*)&outW1[kb] = wh;
                *(uint2*)&outW2[kb] = wl;
            }
        }
    }
}

// ---------------------------------------------------------------------------
// Flash attention: cp.async double-buffered K/V, ldmatrix QK, vectorized PV.
// smem word offsets: KsH[st]: st*4352 ([64][68]); KsL[st]: 8704+st*4352;
// Vs[st]: 17408+st*8448 ([64][132]); Ps: 34304 ([128][68]). Total 172032 B.
// ---------------------------------------------------------------------------
__global__ void __launch_bounds__(256, 1)
flash_attn_tc(const float* __restrict__ q,
              const uint32_t* __restrict__ kh,
              const uint32_t* __restrict__ kl,
              const uint32_t* __restrict__ vv,
              float* __restrict__ o)
{
    extern __shared__ uint32_t usm[];
    uint32_t sbase;
    asm("{ .reg .u64 tt; cvta.to.shared.u64 tt, %1; cvt.u32.u64 %0, tt; }"
        : "=r"(sbase) : "l"(usm));

    const int h  = blockIdx.y;
    const int q0 = blockIdx.x * 128;
    const int t  = threadIdx.x;
    const int warp = t >> 5;
    const int lane = t & 31;
    const int g   = lane >> 2;
    const int tig = lane & 3;
    const int r0 = warp * 16 + g;
    const int r1 = r0 + 8;
    const float scale = 0.08838834764831845f;

    uint32_t* Ps = usm + 34304;

    // ldmatrix per-lane addressing config
    const int rowsel = (lane & 7) + ((lane >> 4) & 1) * 8;   // 0..15
    const int halfw  = ((lane >> 3) & 1) * 4;                // word offset 0/4

    // Q -> bf16 hi+lo regs (pre-scaled)
    uint32_t qh[8][4], ql[8][4];
    {
        const float* qr0 = &q[((size_t)(q0 + r0) * HH + h) * DD];
        const float* qr1 = &q[((size_t)(q0 + r1) * HH + h) * DD];
#pragma unroll
        for (int ks = 0; ks < 8; ks++) {
            int c = ks * 16 + 2 * tig;
            float a0 = qr0[c] * scale,     a1 = qr0[c + 1] * scale;
            float b0 = qr1[c] * scale,     b1 = qr1[c + 1] * scale;
            float c0 = qr0[c + 8] * scale, c1 = qr0[c + 9] * scale;
            float d0 = qr1[c + 8] * scale, d1 = qr1[c + 9] * scale;
            qh[ks][0] = bfpack(a0, a1);
            qh[ks][1] = bfpack(b0, b1);
            qh[ks][2] = bfpack(c0, c1);
            qh[ks][3] = bfpack(d0, d1);
            ql[ks][0] = bfpack(bfres(a0), bfres(a1));
            ql[ks][1] = bfpack(bfres(b0), bfres(b1));
            ql[ks][2] = bfpack(bfres(c0), bfres(c1));
            ql[ks][3] = bfpack(bfres(d0), bfres(d1));
        }
    }

    float m0r = -1e30f, m1r = -1e30f, l0 = 0.0f, l1 = 0.0f;
    float oacc[16][4];
#pragma unroll
    for (int j = 0; j < 16; j++)
#pragma unroll
        for (int e = 0; e < 4; e++) oacc[j][e] = 0.0f;

    // async fill of one stage
    auto fill = [&](int st, int kv) {
        const uint32_t dKH = sbase + (st * 4352) * 4;
        const uint32_t dKL = sbase + (8704 + st * 4352) * 4;
        const uint32_t dV  = sbase + (17408 + st * 8448) * 4;
#pragma unroll
        for (int i = 0; i < 4; i++) {
            int c = i * 256 + t; int r = c >> 4, w = (c & 15) * 4;
            CP16(dKH + (uint32_t)(r * 68 + w) * 4,
                 &kh[((size_t)(kv + r) * HH + h) * 64 + w]);
        }
#pragma unroll
        for (int i = 0; i < 4; i++) {
            int c = i * 256 + t; int r = c >> 4, w = (c & 15) * 4;
            CP16(dKL + (uint32_t)(r * 68 + w) * 4,
                 &kl[((size_t)(kv + r) * HH + h) * 64 + w]);
        }
#pragma unroll
        for (int i = 0; i < 8; i++) {
            int c = i * 256 + t; int r = c >> 5, w = (c & 31) * 4;
            CP16(dV + (uint32_t)(r * 132 + w) * 4,
                 &vv[((size_t)(kv + r) * HH + h) * 128 + w]);
        }
    };

    fill(0, 0);
    CP_COMMIT();

    for (int kv0 = 0; kv0 < SS; kv0 += 64) {
        const int st = (kv0 >> 6) & 1;
        const bool more = (kv0 + 64) < SS;

        if (more) { fill(st ^ 1, kv0 + 64); CP_COMMIT(); }

        if (more) { asm volatile("cp.async.wait_group 1;" ::: "memory"); }
        else      { asm volatile("cp.async.wait_group 0;" ::: "memory"); }
        __syncthreads();   // stage st visible to all threads

        const uint32_t bKH = sbase + (st * 4352) * 4;
        const uint32_t bKL = sbase + (8704 + st * 4352) * 4;
        uint32_t* VsSt = usm + 17408 + st * 8448;

        // ---- QK: bf16x3, ldmatrix.x4 B-operands ----
        float sacc[8][4];
#pragma unroll
        for (int j = 0; j < 8; j++)
#pragma unroll
            for (int e = 0; e < 4; e++) sacc[j][e] = 0.0f;

#pragma unroll
        for (int ks = 0; ks < 8; ks++) {
#pragma unroll
            for (int jp = 0; jp < 4; jp++) {
                uint32_t woff = (uint32_t)((jp * 16 + rowsel) * 68 + ks * 8 + halfw) * 4;
                uint32_t h0, h1, h2, h3, l0r, l1r, l2r, l3r;
                ldsm_x4(bKH + woff, h0, h1, h2, h3);
                ldsm_x4(bKL + woff, l0r, l1r, l2r, l3r);
                mma16(sacc[2 * jp],     ql[ks], h0, h1);
                mma16(sacc[2 * jp],     qh[ks], l0r, l1r);
                mma16(sacc[2 * jp],     qh[ks], h0, h1);
                mma16(sacc[2 * jp + 1], ql[ks], h2, h3);
                mma16(sacc[2 * jp + 1], qh[ks], l2r, l3r);
                mma16(sacc[2 * jp + 1], qh[ks], h2, h3);
            }
        }

        // ---- online softmax ----
        float rmax0 = -1e30f, rmax1 = -1e30f;
#pragma unroll
        for (int j = 0; j < 8; j++) {
            rmax0 = fmaxf(rmax0, fmaxf(sacc[j][0], sacc[j][1]));
            rmax1 = fmaxf(rmax1, fmaxf(sacc[j][2], sacc[j][3]));
        }
#pragma unroll
        for (int off = 1; off < 4; off <<= 1) {
            rmax0 = fmaxf(rmax0, __shfl_xor_sync(0xffffffffu, rmax0, off));
            rmax1 = fmaxf(rmax1, __shfl_xor_sync(0xffffffffu, rmax1, off));
        }
        float mn0 = fmaxf(m0r, rmax0);
        float mn1 = fmaxf(m1r, rmax1);
        float cr0 = __expf(m0r - mn0);
        float cr1 = __expf(m1r - mn1);
        float rs0 = 0.0f, rs1 = 0.0f;
#pragma unroll
        for (int j = 0; j < 8; j++) {
            float e0 = __expf(sacc[j][0] - mn0);
            float e1 = __expf(sacc[j][1] - mn0);
            float e2 = __expf(sacc[j][2] - mn1);
            float e3 = __expf(sacc[j][3] - mn1);
            rs0 += e0 + e1;
            rs1 += e2 + e3;
            int col = j * 8 + 2 * tig;
            Ps[r0 * 68 + col]     = f2tf32(e0);
            Ps[r0 * 68 + col + 1] = f2tf32(e1);
            Ps[r1 * 68 + col]     = f2tf32(e2);
            Ps[r1 * 68 + col + 1] = f2tf32(e3);
        }
#pragma unroll
        for (int off = 1; off < 4; off <<= 1) {
            rs0 += __shfl_xor_sync(0xffffffffu, rs0, off);
            rs1 += __shfl_xor_sync(0xffffffffu, rs1, off);
        }
        l0 = l0 * cr0 + rs0;
        l1 = l1 * cr1 + rs1;
        m0r = mn0;
        m1r = mn1;
#pragma unroll
        for (int j = 0; j < 16; j++) {
            oacc[j][0] *= cr0; oacc[j][1] *= cr0;
            oacc[j][2] *= cr1; oacc[j][3] *= cr1;
        }
        __syncwarp();   // Ps rows r0/r1 warp-private

        // ---- PV: 1xTF32, vectorized Vs loads ----
#pragma unroll
        for (int kc = 0; kc < 8; kc++) {
            uint32_t a[4];
            a[0] = Ps[r0 * 68 + kc * 8 + tig];
            a[1] = Ps[r1 * 68 + kc * 8 + tig];
            a[2] = Ps[r0 * 68 + kc * 8 + tig + 4];
            a[3] = Ps[r1 * 68 + kc * 8 + tig + 4];
            const int row0 = kc * 8 + tig, row1 = row0 + 4;
            uint32_t vb0[16], vb1[16];
#pragma unroll
            for (int jq = 0; jq < 4; jq++) {
                *(uint4*)&vb0[jq * 4] = *(uint4*)&VsSt[row0 * 132 + g * 16 + jq * 4];
                *(uint4*)&vb1[jq * 4] = *(uint4*)&VsSt[row1 * 132 + g * 16 + jq * 4];
            }
#pragma unroll
            for (int j = 0; j < 16; j++)
                mma8(oacc[j], a, vb0[j], vb1[j]);
        }
        __syncthreads();   // all done with stage st before next iter's fill
    }

    // epilogue
    float inv0 = 1.0f / l0, inv1 = 1.0f / l1;
    float* o0 = &o[((size_t)(q0 + r0) * HH + h) * DD];
    float* o1 = &o[((size_t)(q0 + r1) * HH + h) * DD];
#pragma unroll
    for (int j = 0; j < 16; j++) {
        int col = j * 8 + 2 * tig;
        float2 s0 = make_float2(oacc[j][0] * inv0, oacc[j][1] * inv0);
        float2 s1 = make_float2(oacc[j][2] * inv1, oacc[j][3] * inv1);
        *(float2*)&o0[col] = s0;
        *(float2*)&o1[col] = s1;
    }
}

// ---------------------------------------------------------------------------
extern "C" void kernel_launch(void* const* d_in, const int* in_sizes, int n_in,
                              void* d_out, int out_size)
{
    const float* x    = (const float*)d_in[0];
    const float* rope = (const float*)d_in[1];
    const float* Wq   = (const float*)d_in[2];
    const float* bq   = (const float*)d_in[3];
    const float* Wk   = (const float*)d_in[4];
    const float* bk   = (const float*)d_in[5];
    const float* Wv   = (const float*)d_in[6];
    const float* bv   = (const float*)d_in[7];
    const float* qn_w = (const float*)d_in[8];
    const float* kn_w = (const float*)d_in[9];
    const float* Wo   = (const float*)d_in[10];
    const float* bo   = (const float*)d_in[11];
    float* out = (float*)d_out;

    float *qp, *ap;
    uint32_t *khp, *klp, *vp;
    cudaGetSymbolAddress((void**)&qp,  g_q);
    cudaGetSymbolAddress((void**)&khp, g_kh);
    cudaGetSymbolAddress((void**)&klp, g_kl);
    cudaGetSymbolAddress((void**)&vp,  g_v);
    cudaGetSymbolAddress((void**)&ap,  g_attn);

    const int smem_gemm = 128 * 132 * sizeof(float);   // 67584
    const int smem_attn = 172032;
    cudaFuncSetAttribute(gemm_nt_bf16x3, cudaFuncAttributeMaxDynamicSharedMemorySize,
                         smem_gemm);
    cudaFuncSetAttribute(flash_attn_tc, cudaFuncAttributeMaxDynamicSharedMemorySize,
                         smem_attn);

    dim3 ggrid(CC / 128, SS / 128);
    // Q: norm+rope -> fp32
    gemm_nt_bf16x3<<<ggrid, 256, smem_gemm>>>(x, Wq, bq, qp, nullptr, nullptr,
                                              qn_w, rope, 1, SS, CC, CC);
    // K: norm+rope -> packed bf16 hi/lo
    gemm_nt_bf16x3<<<ggrid, 256, smem_gemm>>>(x, Wk, bk, nullptr, khp, klp,
                                              kn_w, rope, 2, SS, CC, CC);
    // V: plain -> tf32 d'-interleaved
    gemm_nt_bf16x3<<<ggrid, 256, smem_gemm>>>(x, Wv, bv, nullptr, vp, nullptr,
                                              nullptr, nullptr, 3, SS, CC, CC);

    dim3 agrid(SS / 128, HH);
    flash_attn_tc<<<agrid, 256, smem_attn>>>(qp, khp, klp, vp, ap);

    // final projection: plain fp32
    gemm_nt_bf16x3<<<ggrid, 256, smem_gemm>>>(ap, Wo, bo, out, nullptr, nullptr,
                                              nullptr, nullptr, 0, SS, CC, CC);
}

// round 9
// speedup vs baseline: 2.8478x; 1.2285x over previous
#include <cuda_runtime.h>
#include <cstdint>
#include <cuda_bf16.h>
#include <mma.h>
#include <math.h>

using namespace nvcuda;

#define SS 4096
#define CC 2048
#define HH 16
#define DD 128
#define EPSF 1.1920929e-07f

typedef __nv_bfloat16 bf16;

// Scratch (no cudaMalloc allowed)
__device__ float    g_q[SS * CC];            // Q fp32 (post norm+rope)
__device__ uint32_t g_kh[SS * HH * 64];      // K hi, packed bf16x2 (d pairs)
__device__ uint32_t g_kl[SS * HH * 64];      // K lo, packed bf16x2
__device__ uint32_t g_v[SS * HH * 128];      // V tf32 words, d' = (d&7)*16+(d>>3)
__device__ float    g_attn[SS * CC];         // attention output fp32
// pre-split bf16 hi/lo operands
__device__ bf16 g_xh[SS * CC],  g_xl[SS * CC];
__device__ bf16 g_ah[SS * CC],  g_al[SS * CC];
__device__ bf16 g_wqh[CC * CC], g_wql[CC * CC];
__device__ bf16 g_wkh[CC * CC], g_wkl[CC * CC];
__device__ bf16 g_wvh[CC * CC], g_wvl[CC * CC];
__device__ bf16 g_woh[CC * CC], g_wol[CC * CC];

// ---------------------------------------------------------------------------
// helpers
// ---------------------------------------------------------------------------
__device__ __forceinline__ uint32_t f2tf32(float x) {
    uint32_t r;
    asm("cvt.rna.tf32.f32 %0, %1;\n" : "=r"(r) : "f"(x));
    return r;
}
__device__ __forceinline__ uint32_t bfpack(float x, float y) {
    __nv_bfloat162 h = __floats2bfloat162_rn(x, y);
    return *(uint32_t*)&h;
}
__device__ __forceinline__ float bfres(float x) {
    return x - __bfloat162float(__float2bfloat16_rn(x));
}

__device__ __forceinline__ void mma8(float* c, const uint32_t* a,
                                     uint32_t b0, uint32_t b1) {
    asm volatile(
        "mma.sync.aligned.m16n8k8.row.col.f32.tf32.tf32.f32 "
        "{%0,%1,%2,%3}, {%4,%5,%6,%7}, {%8,%9}, {%0,%1,%2,%3};\n"
        : "+f"(c[0]), "+f"(c[1]), "+f"(c[2]), "+f"(c[3])
        : "r"(a[0]), "r"(a[1]), "r"(a[2]), "r"(a[3]), "r"(b0), "r"(b1));
}
__device__ __forceinline__ void mma16(float* c, const uint32_t* a,
                                      uint32_t b0, uint32_t b1) {
    asm volatile(
        "mma.sync.aligned.m16n8k16.row.col.f32.bf16.bf16.f32 "
        "{%0,%1,%2,%3}, {%4,%5,%6,%7}, {%8,%9}, {%0,%1,%2,%3};\n"
        : "+f"(c[0]), "+f"(c[1]), "+f"(c[2]), "+f"(c[3])
        : "r"(a[0]), "r"(a[1]), "r"(a[2]), "r"(a[3]), "r"(b0), "r"(b1));
}

#define CP16(dst_u32, src_ptr) \
    asm volatile("cp.async.cg.shared.global [%0], [%1], 16;" \
                 :: "r"(dst_u32), "l"(src_ptr) : "memory")
#define CP_COMMIT() asm volatile("cp.async.commit_group;" ::: "memory")

__device__ __forceinline__ void ldsm_x4(uint32_t addr, uint32_t& r0, uint32_t& r1,
                                        uint32_t& r2, uint32_t& r3) {
    asm volatile("ldmatrix.sync.aligned.m8n8.x4.shared.b16 {%0,%1,%2,%3}, [%4];"
                 : "=r"(r0), "=r"(r1), "=r"(r2), "=r"(r3) : "r"(addr));
}

// ---------------------------------------------------------------------------
// split fp32 -> bf16 hi + lo residual (elementwise, float4 granularity)
// ---------------------------------------------------------------------------
__global__ void split_bf16(const float* __restrict__ in,
                           bf16* __restrict__ oh, bf16* __restrict__ ol, int n)
{
    int i = (blockIdx.x * 256 + threadIdx.x) * 4;
    if (i >= n) return;
    float4 v = *(const float4*)&in[i];
    uint2 h = make_uint2(bfpack(v.x, v.y), bfpack(v.z, v.w));
    uint2 l = make_uint2(bfpack(bfres(v.x), bfres(v.y)),
                         bfpack(bfres(v.z), bfres(v.w)));
    *(uint2*)&oh[i] = h;
    *(uint2*)&ol[i] = l;
}

// ---------------------------------------------------------------------------
// Lean GEMM on pre-split bf16 operands: Out[M,N] = A @ B^T + bias.
// cp.async 2-stage pipeline, 128x128x32 tile, 256 thr, 2 CTAs/SM.
// stage layout (bytes): Ah +0, Al +10240, Bh +20480, Bl +30720 (rows of 40 bf16)
// mode 0: fp32 out  1: norm+rope fp32 (Q)  2: norm+rope packed K  3: tf32 V
// ---------------------------------------------------------------------------
__global__ void __launch_bounds__(256, 2)
gemm_pre(const bf16* __restrict__ Ah, const bf16* __restrict__ Al,
         const bf16* __restrict__ Bh, const bf16* __restrict__ Bl,
         const float* __restrict__ bias,
         float* __restrict__ Out,
         uint32_t* __restrict__ outW1, uint32_t* __restrict__ outW2,
         const float* __restrict__ normw, const float* __restrict__ rope,
         int mode, int M, int N, int K)
{
    extern __shared__ char smemc[];
    uint32_t sbase;
    asm("{ .reg .u64 tt; cvta.to.shared.u64 tt, %1; cvt.u32.u64 %0, tt; }"
        : "=r"(sbase) : "l"(smemc));

    const int t = threadIdx.x;
    const int warp = t >> 5;
    const int wr = warp >> 2;
    const int wc = warp & 3;
    const int m0 = blockIdx.y * 128;
    const int n0 = blockIdx.x * 128;
    const int hh = blockIdx.x;

    wmma::fragment<wmma::accumulator, 16, 16, 16, float> cfrag[4][2];
#pragma unroll
    for (int mi = 0; mi < 4; mi++)
#pragma unroll
        for (int nj = 0; nj < 2; nj++) wmma::fill_fragment(cfrag[mi][nj], 0.0f);

    // async fill of one stage (4 arrays x 128x32 bf16; 8 CP16 per thread)
    auto fill = [&](int st, int k0) {
        const uint32_t base = sbase + st * 40960;
#pragma unroll
        for (int i = 0; i < 2; i++) {
            int c = i * 256 + t;
            int r = c >> 2, ch = c & 3;
            uint32_t off = (uint32_t)(r * 80 + ch * 16);
            size_t ga = (size_t)(m0 + r) * K + k0 + ch * 8;
            size_t gb = (size_t)(n0 + r) * K + k0 + ch * 8;
            CP16(base + off,         &Ah[ga]);
            CP16(base + 10240 + off, &Al[ga]);
            CP16(base + 20480 + off, &Bh[gb]);
            CP16(base + 30720 + off, &Bl[gb]);
        }
    };

    fill(0, 0);
    CP_COMMIT();

    for (int k0 = 0; k0 < K; k0 += 32) {
        const int st = (k0 >> 5) & 1;
        asm volatile("cp.async.wait_group 0;" ::: "memory");
        __syncthreads();
        if (k0 + 32 < K) { fill(st ^ 1, k0 + 32); CP_COMMIT(); }

        bf16* Ash = (bf16*)(smemc + st * 40960);
        bf16* Asl = Ash + 5120;
        bf16* Bsh = Ash + 10240;
        bf16* Bsl = Ash + 15360;

#pragma unroll
        for (int ks = 0; ks < 2; ks++) {
            wmma::fragment<wmma::matrix_b, 16, 16, 16, bf16, wmma::col_major> bh[2], bl[2];
#pragma unroll
            for (int nj = 0; nj < 2; nj++) {
                wmma::load_matrix_sync(bh[nj], &Bsh[(wc * 32 + nj * 16) * 40 + ks * 16], 40);
                wmma::load_matrix_sync(bl[nj], &Bsl[(wc * 32 + nj * 16) * 40 + ks * 16], 40);
            }
#pragma unroll
            for (int mi = 0; mi < 4; mi++) {
                wmma::fragment<wmma::matrix_a, 16, 16, 16, bf16, wmma::row_major> ah, al;
                wmma::load_matrix_sync(ah, &Ash[(wr * 64 + mi * 16) * 40 + ks * 16], 40);
                wmma::load_matrix_sync(al, &Asl[(wr * 64 + mi * 16) * 40 + ks * 16], 40);
#pragma unroll
                for (int nj = 0; nj < 2; nj++) {
                    wmma::mma_sync(cfrag[mi][nj], al, bh[nj], cfrag[mi][nj]);
                    wmma::mma_sync(cfrag[mi][nj], ah, bl[nj], cfrag[mi][nj]);
                    wmma::mma_sync(cfrag[mi][nj], ah, bh[nj], cfrag[mi][nj]);
                }
            }
        }
    }
    __syncthreads();

    // epilogue: stage to smem, then mode-specific output
    float* Cs = (float*)smemc;  // [128][132] = 67584 B <= 81920 B
#pragma unroll
    for (int mi = 0; mi < 4; mi++)
#pragma unroll
        for (int nj = 0; nj < 2; nj++)
            wmma::store_matrix_sync(&Cs[(wr * 64 + mi * 16) * 132 + wc * 32 + nj * 16],
                                    cfrag[mi][nj], 132, wmma::mem_row_major);
    __syncthreads();

    if (mode == 0) {
#pragma unroll
        for (int i = 0; i < 16; i++) {
            int idx = i * 256 + t;
            int r = idx >> 5, c4 = (idx & 31) * 4;
            float4 cv = *(float4*)&Cs[r * 132 + c4];
            float4 bb = *(const float4*)&bias[n0 + c4];
            cv.x += bb.x; cv.y += bb.y; cv.z += bb.z; cv.w += bb.w;
            *(float4*)&Out[(size_t)(m0 + r) * N + n0 + c4] = cv;
        }
    } else if (mode == 3) {
#pragma unroll
        for (int i = 0; i < 16; i++) {
            int idx = i * 256 + t;
            int r = idx >> 5, c4 = (idx & 31) * 4;
            float4 cv = *(float4*)&Cs[r * 132 + c4];
            float4 bb = *(const float4*)&bias[n0 + c4];
            cv.x += bb.x; cv.y += bb.y; cv.z += bb.z; cv.w += bb.w;
            size_t base = ((size_t)(m0 + r) * HH + hh) * 128;
            float vals[4] = {cv.x, cv.y, cv.z, cv.w};
#pragma unroll
            for (int e = 0; e < 4; e++) {
                int d = c4 + e;
                int dp = (d & 7) * 16 + (d >> 3);
                outW1[base + dp] = f2tf32(vals[e]);
            }
        }
    } else {
        const int r = t >> 1, half = t & 1;
        const int s = m0 + r;
        float* row = &Cs[r * 132 + half * 64];
        const float* bias_h = &bias[n0 + half * 64];
        float ssq = 0.0f;
#pragma unroll
        for (int j = 0; j < 16; j++) {
            float4 c = ((float4*)row)[j];
            float4 bb = ((const float4*)bias_h)[j];
            c.x += bb.x; c.y += bb.y; c.z += bb.z; c.w += bb.w;
            ((float4*)row)[j] = c;
            ssq += c.x * c.x + c.y * c.y + c.z * c.z + c.w * c.w;
        }
        ssq += __shfl_xor_sync(0xffffffffu, ssq, 1);
        float inv = rsqrtf(ssq * (1.0f / 128.0f) + EPSF);
        const float* wv = &normw[half * 64];
        const float* rp = &rope[(size_t)s * 256 + half * 128];
        float* outp = &Out[(size_t)(m0 + r) * N + n0 + half * 64];
#pragma unroll
        for (int j = 0; j < 16; j++) {
            float4 c = ((float4*)row)[j];
            float4 ww = ((const float4*)wv)[j];
            float x0 = c.x * inv * ww.x;
            float x1 = c.y * inv * ww.y;
            float x2 = c.z * inv * ww.z;
            float x3 = c.w * inv * ww.w;
            float4 rA = ((const float4*)rp)[2 * j];
            float4 rB = ((const float4*)rp)[2 * j + 1];
            float4 ov;
            ov.x = rA.x * x0 + rA.y * x1;
            ov.y = rA.z * x0 + rA.w * x1;
            ov.z = rB.x * x2 + rB.y * x3;
            ov.w = rB.z * x2 + rB.w * x3;
            if (mode == 1) {
                ((float4*)outp)[j] = ov;
            } else {
                size_t kb = ((size_t)s * HH + hh) * 64 + half * 32 + j * 2;
                uint2 wh = make_uint2(bfpack(ov.x, ov.y), bfpack(ov.z, ov.w));
                uint2 wl = make_uint2(bfpack(bfres(ov.x), bfres(ov.y)),
                                      bfpack(bfres(ov.z), bfres(ov.w)));
                *(uint2*)&outW1[kb] = wh;
                *(uint2*)&outW2[kb] = wl;
            }
        }
    }
}

// ---------------------------------------------------------------------------
// Flash attention (unchanged from R8): cp.async double-buffered K/V,
// ldmatrix QK (bf16x3), vectorized PV (1xTF32).
// ---------------------------------------------------------------------------
__global__ void __launch_bounds__(256, 1)
flash_attn_tc(const float* __restrict__ q,
              const uint32_t* __restrict__ kh,
              const uint32_t* __restrict__ kl,
              const uint32_t* __restrict__ vv,
              float* __restrict__ o)
{
    extern __shared__ uint32_t usm[];
    uint32_t sbase;
    asm("{ .reg .u64 tt; cvta.to.shared.u64 tt, %1; cvt.u32.u64 %0, tt; }"
        : "=r"(sbase) : "l"(usm));

    const int h  = blockIdx.y;
    const int q0 = blockIdx.x * 128;
    const int t  = threadIdx.x;
    const int warp = t >> 5;
    const int lane = t & 31;
    const int g   = lane >> 2;
    const int tig = lane & 3;
    const int r0 = warp * 16 + g;
    const int r1 = r0 + 8;
    const float scale = 0.08838834764831845f;

    uint32_t* Ps = usm + 34304;

    const int rowsel = (lane & 7) + ((lane >> 4) & 1) * 8;
    const int halfw  = ((lane >> 3) & 1) * 4;

    uint32_t qh[8][4], ql[8][4];
    {
        const float* qr0 = &q[((size_t)(q0 + r0) * HH + h) * DD];
        const float* qr1 = &q[((size_t)(q0 + r1) * HH + h) * DD];
#pragma unroll
        for (int ks = 0; ks < 8; ks++) {
            int c = ks * 16 + 2 * tig;
            float a0 = qr0[c] * scale,     a1 = qr0[c + 1] * scale;
            float b0 = qr1[c] * scale,     b1 = qr1[c + 1] * scale;
            float c0 = qr0[c + 8] * scale, c1 = qr0[c + 9] * scale;
            float d0 = qr1[c + 8] * scale, d1 = qr1[c + 9] * scale;
            qh[ks][0] = bfpack(a0, a1);
            qh[ks][1] = bfpack(b0, b1);
            qh[ks][2] = bfpack(c0, c1);
            qh[ks][3] = bfpack(d0, d1);
            ql[ks][0] = bfpack(bfres(a0), bfres(a1));
            ql[ks][1] = bfpack(bfres(b0), bfres(b1));
            ql[ks][2] = bfpack(bfres(c0), bfres(c1));
            ql[ks][3] = bfpack(bfres(d0), bfres(d1));
        }
    }

    float m0r = -1e30f, m1r = -1e30f, l0 = 0.0f, l1 = 0.0f;
    float oacc[16][4];
#pragma unroll
    for (int j = 0; j < 16; j++)
#pragma unroll
        for (int e = 0; e < 4; e++) oacc[j][e] = 0.0f;

    auto fill = [&](int st, int kv) {
        const uint32_t dKH = sbase + (st * 4352) * 4;
        const uint32_t dKL = sbase + (8704 + st * 4352) * 4;
        const uint32_t dV  = sbase + (17408 + st * 8448) * 4;
#pragma unroll
        for (int i = 0; i < 4; i++) {
            int c = i * 256 + t; int r = c >> 4, w = (c & 15) * 4;
            CP16(dKH + (uint32_t)(r * 68 + w) * 4,
                 &kh[((size_t)(kv + r) * HH + h) * 64 + w]);
        }
#pragma unroll
        for (int i = 0; i < 4; i++) {
            int c = i * 256 + t; int r = c >> 4, w = (c & 15) * 4;
            CP16(dKL + (uint32_t)(r * 68 + w) * 4,
                 &kl[((size_t)(kv + r) * HH + h) * 64 + w]);
        }
#pragma unroll
        for (int i = 0; i < 8; i++) {
            int c = i * 256 + t; int r = c >> 5, w = (c & 31) * 4;
            CP16(dV + (uint32_t)(r * 132 + w) * 4,
                 &vv[((size_t)(kv + r) * HH + h) * 128 + w]);
        }
    };

    fill(0, 0);
    CP_COMMIT();

    for (int kv0 = 0; kv0 < SS; kv0 += 64) {
        const int st = (kv0 >> 6) & 1;
        const bool more = (kv0 + 64) < SS;

        if (more) { fill(st ^ 1, kv0 + 64); CP_COMMIT(); }

        if (more) { asm volatile("cp.async.wait_group 1;" ::: "memory"); }
        else      { asm volatile("cp.async.wait_group 0;" ::: "memory"); }
        __syncthreads();

        const uint32_t bKH = sbase + (st * 4352) * 4;
        const uint32_t bKL = sbase + (8704 + st * 4352) * 4;
        uint32_t* VsSt = usm + 17408 + st * 8448;

        float sacc[8][4];
#pragma unroll
        for (int j = 0; j < 8; j++)
#pragma unroll
            for (int e = 0; e < 4; e++) sacc[j][e] = 0.0f;

#pragma unroll
        for (int ks = 0; ks < 8; ks++) {
#pragma unroll
            for (int jp = 0; jp < 4; jp++) {
                uint32_t woff = (uint32_t)((jp * 16 + rowsel) * 68 + ks * 8 + halfw) * 4;
                uint32_t h0, h1, h2, h3, l0r, l1r, l2r, l3r;
                ldsm_x4(bKH + woff, h0, h1, h2, h3);
                ldsm_x4(bKL + woff, l0r, l1r, l2r, l3r);
                mma16(sacc[2 * jp],     ql[ks], h0, h1);
                mma16(sacc[2 * jp],     qh[ks], l0r, l1r);
                mma16(sacc[2 * jp],     qh[ks], h0, h1);
                mma16(sacc[2 * jp + 1], ql[ks], h2, h3);
                mma16(sacc[2 * jp + 1], qh[ks], l2r, l3r);
                mma16(sacc[2 * jp + 1], qh[ks], h2, h3);
            }
        }

        float rmax0 = -1e30f, rmax1 = -1e30f;
#pragma unroll
        for (int j = 0; j < 8; j++) {
            rmax0 = fmaxf(rmax0, fmaxf(sacc[j][0], sacc[j][1]));
            rmax1 = fmaxf(rmax1, fmaxf(sacc[j][2], sacc[j][3]));
        }
#pragma unroll
        for (int off = 1; off < 4; off <<= 1) {
            rmax0 = fmaxf(rmax0, __shfl_xor_sync(0xffffffffu, rmax0, off));
            rmax1 = fmaxf(rmax1, __shfl_xor_sync(0xffffffffu, rmax1, off));
        }
        float mn0 = fmaxf(m0r, rmax0);
        float mn1 = fmaxf(m1r, rmax1);
        float cr0 = __expf(m0r - mn0);
        float cr1 = __expf(m1r - mn1);
        float rs0 = 0.0f, rs1 = 0.0f;
#pragma unroll
        for (int j = 0; j < 8; j++) {
            float e0 = __expf(sacc[j][0] - mn0);
            float e1 = __expf(sacc[j][1] - mn0);
            float e2 = __expf(sacc[j][2] - mn1);
            float e3 = __expf(sacc[j][3] - mn1);
            rs0 += e0 + e1;
            rs1 += e2 + e3;
            int col = j * 8 + 2 * tig;
            Ps[r0 * 68 + col]     = f2tf32(e0);
            Ps[r0 * 68 + col + 1] = f2tf32(e1);
            Ps[r1 * 68 + col]     = f2tf32(e2);
            Ps[r1 * 68 + col + 1] = f2tf32(e3);
        }
#pragma unroll
        for (int off = 1; off < 4; off <<= 1) {
            rs0 += __shfl_xor_sync(0xffffffffu, rs0, off);
            rs1 += __shfl_xor_sync(0xffffffffu, rs1, off);
        }
        l0 = l0 * cr0 + rs0;
        l1 = l1 * cr1 + rs1;
        m0r = mn0;
        m1r = mn1;
#pragma unroll
        for (int j = 0; j < 16; j++) {
            oacc[j][0] *= cr0; oacc[j][1] *= cr0;
            oacc[j][2] *= cr1; oacc[j][3] *= cr1;
        }
        __syncwarp();

#pragma unroll
        for (int kc = 0; kc < 8; kc++) {
            uint32_t a[4];
            a[0] = Ps[r0 * 68 + kc * 8 + tig];
            a[1] = Ps[r1 * 68 + kc * 8 + tig];
            a[2] = Ps[r0 * 68 + kc * 8 + tig + 4];
            a[3] = Ps[r1 * 68 + kc * 8 + tig + 4];
            const int row0 = kc * 8 + tig, row1 = row0 + 4;
            uint32_t vb0[16], vb1[16];
#pragma unroll
            for (int jq = 0; jq < 4; jq++) {
                *(uint4*)&vb0[jq * 4] = *(uint4*)&VsSt[row0 * 132 + g * 16 + jq * 4];
                *(uint4*)&vb1[jq * 4] = *(uint4*)&VsSt[row1 * 132 + g * 16 + jq * 4];
            }
#pragma unroll
            for (int j = 0; j < 16; j++)
                mma8(oacc[j], a, vb0[j], vb1[j]);
        }
        __syncthreads();
    }

    float inv0 = 1.0f / l0, inv1 = 1.0f / l1;
    float* o0 = &o[((size_t)(q0 + r0) * HH + h) * DD];
    float* o1 = &o[((size_t)(q0 + r1) * HH + h) * DD];
#pragma unroll
    for (int j = 0; j < 16; j++) {
        int col = j * 8 + 2 * tig;
        float2 s0 = make_float2(oacc[j][0] * inv0, oacc[j][1] * inv0);
        float2 s1 = make_float2(oacc[j][2] * inv1, oacc[j][3] * inv1);
        *(float2*)&o0[col] = s0;
        *(float2*)&o1[col] = s1;
    }
}

// ---------------------------------------------------------------------------
extern "C" void kernel_launch(void* const* d_in, const int* in_sizes, int n_in,
                              void* d_out, int out_size)
{
    const float* x    = (const float*)d_in[0];
    const float* rope = (const float*)d_in[1];
    const float* Wq   = (const float*)d_in[2];
    const float* bq   = (const float*)d_in[3];
    const float* Wk   = (const float*)d_in[4];
    const float* bk   = (const float*)d_in[5];
    const float* Wv   = (const float*)d_in[6];
    const float* bv   = (const float*)d_in[7];
    const float* qn_w = (const float*)d_in[8];
    const float* kn_w = (const float*)d_in[9];
    const float* Wo   = (const float*)d_in[10];
    const float* bo   = (const float*)d_in[11];
    float* out = (float*)d_out;

    float *qp, *ap;
    uint32_t *khp, *klp, *vp;
    bf16 *xh, *xl, *ah, *al;
    bf16 *wqh, *wql, *wkh, *wkl, *wvh, *wvl, *woh, *wol;
    cudaGetSymbolAddress((void**)&qp,  g_q);
    cudaGetSymbolAddress((void**)&khp, g_kh);
    cudaGetSymbolAddress((void**)&klp, g_kl);
    cudaGetSymbolAddress((void**)&vp,  g_v);
    cudaGetSymbolAddress((void**)&ap,  g_attn);
    cudaGetSymbolAddress((void**)&xh,  g_xh);
    cudaGetSymbolAddress((void**)&xl,  g_xl);
    cudaGetSymbolAddress((void**)&ah,  g_ah);
    cudaGetSymbolAddress((void**)&al,  g_al);
    cudaGetSymbolAddress((void**)&wqh, g_wqh);
    cudaGetSymbolAddress((void**)&wql, g_wql);
    cudaGetSymbolAddress((void**)&wkh, g_wkh);
    cudaGetSymbolAddress((void**)&wkl, g_wkl);
    cudaGetSymbolAddress((void**)&wvh, g_wvh);
    cudaGetSymbolAddress((void**)&wvl, g_wvl);
    cudaGetSymbolAddress((void**)&woh, g_woh);
    cudaGetSymbolAddress((void**)&wol, g_wol);

    const int smem_gemm = 81920;
    const int smem_attn = 172032;
    cudaFuncSetAttribute(gemm_pre, cudaFuncAttributeMaxDynamicSharedMemorySize,
                         smem_gemm);
    cudaFuncSetAttribute(flash_attn_tc, cudaFuncAttributeMaxDynamicSharedMemorySize,
                         smem_attn);

    const int nx = SS * CC, nw = CC * CC;
    split_bf16<<<nx / 1024, 256>>>(x,  xh,  xl,  nx);
    split_bf16<<<nw / 1024, 256>>>(Wq, wqh, wql, nw);
    split_bf16<<<nw / 1024, 256>>>(Wk, wkh, wkl, nw);
    split_bf16<<<nw / 1024, 256>>>(Wv, wvh, wvl, nw);
    split_bf16<<<nw / 1024, 256>>>(Wo, woh, wol, nw);

    dim3 ggrid(CC / 128, SS / 128);
    gemm_pre<<<ggrid, 256, smem_gemm>>>(xh, xl, wqh, wql, bq, qp, nullptr, nullptr,
                                        qn_w, rope, 1, SS, CC, CC);
    gemm_pre<<<ggrid, 256, smem_gemm>>>(xh, xl, wkh, wkl, bk, nullptr, khp, klp,
                                        kn_w, rope, 2, SS, CC, CC);
    gemm_pre<<<ggrid, 256, smem_gemm>>>(xh, xl, wvh, wvl, bv, nullptr, vp, nullptr,
                                        nullptr, nullptr, 3, SS, CC, CC);

    dim3 agrid(SS / 128, HH);
    flash_attn_tc<<<agrid, 256, smem_attn>>>(qp, khp, klp, vp, ap);

    split_bf16<<<nx / 1024, 256>>>(ap, ah, al, nx);
    gemm_pre<<<ggrid, 256, smem_gemm>>>(ah, al, woh, wol, bo, out, nullptr, nullptr,
                                        nullptr, nullptr, 0, SS, CC, CC);
}

// round 12
// speedup vs baseline: 3.1762x; 1.1153x over previous
#include <cuda_runtime.h>
#include <cstdint>
#include <cuda_bf16.h>
#include <mma.h>
#include <math.h>

using namespace nvcuda;

#define SS 4096
#define CC 2048
#define HH 16
#define DD 128
#define EPSF 1.1920929e-07f

typedef __nv_bfloat16 bf16;

// Scratch (no cudaMalloc allowed)
__device__ float    g_q[SS * CC];            // Q fp32 (post norm+rope)
__device__ uint32_t g_kh[SS * HH * 64];      // K hi, packed bf16x2 (d pairs)
__device__ uint32_t g_kl[SS * HH * 64];      // K lo, packed bf16x2
__device__ uint32_t g_v[SS * HH * 128];      // V tf32 words, d' = (d&7)*16+(d>>3)
__device__ float    g_attn[SS * CC];         // attention output fp32
// pre-split bf16 hi/lo operands in PADDED TILE-IMAGE layout:
// [tile=row/128][slab=k/32][128 rows x 40 bf16 = 10240 B]  (5/4 padding)
#define PADN(r, c) ((size_t)(r) * (c) * 5 / 4)
__device__ bf16 g_xh[PADN(SS, CC)],  g_xl[PADN(SS, CC)];
__device__ bf16 g_ah[PADN(SS, CC)],  g_al[PADN(SS, CC)];
__device__ bf16 g_wqh[PADN(CC, CC)], g_wql[PADN(CC, CC)];
__device__ bf16 g_wkh[PADN(CC, CC)], g_wkl[PADN(CC, CC)];
__device__ bf16 g_wvh[PADN(CC, CC)], g_wvl[PADN(CC, CC)];
__device__ bf16 g_woh[PADN(CC, CC)], g_wol[PADN(CC, CC)];

#define TILE_ELEMS 327680u    // 64 slabs * 5120 elems
#define SLAB_ELEMS 5120u      // 128 rows * 40 bf16

// ---------------------------------------------------------------------------
// helpers
// ---------------------------------------------------------------------------
__device__ __forceinline__ uint32_t f2tf32(float x) {
    uint32_t r;
    asm("cvt.rna.tf32.f32 %0, %1;\n" : "=r"(r) : "f"(x));
    return r;
}
__device__ __forceinline__ uint32_t bfpack(float x, float y) {
    __nv_bfloat162 h = __floats2bfloat162_rn(x, y);
    return *(uint32_t*)&h;
}
__device__ __forceinline__ float bfres(float x) {
    return x - __bfloat162float(__float2bfloat16_rn(x));
}

__device__ __forceinline__ void mma8(float* c, const uint32_t* a,
                                     uint32_t b0, uint32_t b1) {
    asm volatile(
        "mma.sync.aligned.m16n8k8.row.col.f32.tf32.tf32.f32 "
        "{%0,%1,%2,%3}, {%4,%5,%6,%7}, {%8,%9}, {%0,%1,%2,%3};\n"
        : "+f"(c[0]), "+f"(c[1]), "+f"(c[2]), "+f"(c[3])
        : "r"(a[0]), "r"(a[1]), "r"(a[2]), "r"(a[3]), "r"(b0), "r"(b1));
}
__device__ __forceinline__ void mma16(float* c, const uint32_t* a,
                                      uint32_t b0, uint32_t b1) {
    asm volatile(
        "mma.sync.aligned.m16n8k16.row.col.f32.bf16.bf16.f32 "
        "{%0,%1,%2,%3}, {%4,%5,%6,%7}, {%8,%9}, {%0,%1,%2,%3};\n"
        : "+f"(c[0]), "+f"(c[1]), "+f"(c[2]), "+f"(c[3])
        : "r"(a[0]), "r"(a[1]), "r"(a[2]), "r"(a[3]), "r"(b0), "r"(b1));
}

#define CP16(dst_u32, src_ptr) \
    asm volatile("cp.async.cg.shared.global [%0], [%1], 16;" \
                 :: "r"(dst_u32), "l"(src_ptr) : "memory")
#define CP_COMMIT() asm volatile("cp.async.commit_group;" ::: "memory")

__device__ __forceinline__ void ldsm_x4(uint32_t addr, uint32_t& r0, uint32_t& r1,
                                        uint32_t& r2, uint32_t& r3) {
    asm volatile("ldmatrix.sync.aligned.m8n8.x4.shared.b16 {%0,%1,%2,%3}, [%4];"
                 : "=r"(r0), "=r"(r1), "=r"(r2), "=r"(r3) : "r"(addr));
}

__device__ __forceinline__ uint32_t smem_u32(const void* p) {
    uint32_t a;
    asm("{ .reg .u64 tt; cvta.to.shared.u64 tt, %1; cvt.u32.u64 %0, tt; }"
        : "=r"(a) : "l"(p));
    return a;
}

// --- mbarrier + bulk-DMA primitives (compile-verified on sm_103 in R10) ---
#define MBINIT(m, c) \
    asm volatile("mbarrier.init.shared.b64 [%0], %1;" :: "r"(m), "r"(c) : "memory")
#define MBEXPECT(m, b) \
    asm volatile("mbarrier.arrive.expect_tx.shared.b64 _, [%0], %1;" :: "r"(m), "r"(b) : "memory")
#define BULKCP(dst, src, bytes, mbar) \
    asm volatile("cp.async.bulk.shared::cta.global.mbarrier::complete_tx::bytes [%0], [%1], %2, [%3];" \
                 :: "r"(dst), "l"(src), "r"(bytes), "r"(mbar) : "memory")

#define MBWAIT(mbar_addr, parity) do { \
    uint32_t _m = (mbar_addr), _p = (parity), _d; \
    asm volatile( \
        "{\n\t.reg .pred p;\n\t" \
        "mbarrier.try_wait.parity.acquire.cta.shared::cta.b64 p, [%1], %2;\n\t" \
        "selp.b32 %0, 1, 0, p;\n\t}" \
        : "=r"(_d) : "r"(_m), "r"(_p) : "memory"); \
    if (!_d) { \
        asm volatile( \
            "{\n\t.reg .pred P1;\n\t" \
            "WL_%=:\n\t" \
            "mbarrier.try_wait.parity.acquire.cta.shared::cta.b64 P1, [%0], %1, 0x989680;\n\t" \
            "@P1 bra.uni WD_%=;\n\t" \
            "bra.uni WL_%=;\n\t" \
            "WD_%=:\n\t}" \
            :: "r"(_m), "r"(_p) : "memory"); \
    } \
} while (0)

// ---------------------------------------------------------------------------
// split fp32 -> bf16 hi/lo in padded tile-image layout (rows x 2048 K cols)
// dst elem off = (r>>7)*327680 + (kc>>5)*5120 + (r&127)*40 + (kc&31)
// ---------------------------------------------------------------------------
__global__ void split_sw(const float* __restrict__ in,
                         bf16* __restrict__ oh, bf16* __restrict__ ol)
{
    int idx = blockIdx.x * 256 + threadIdx.x;    // one per 4 elems
    int r  = idx >> 9;           // row
    int kc = (idx & 511) * 4;    // k col
    float4 v = *(const float4*)&in[(size_t)r * 2048 + kc];
    uint2 h = make_uint2(bfpack(v.x, v.y), bfpack(v.z, v.w));
    uint2 l = make_uint2(bfpack(bfres(v.x), bfres(v.y)),
                         bfpack(bfres(v.z), bfres(v.w)));
    size_t off = (size_t)(r >> 7) * TILE_ELEMS + (size_t)(kc >> 5) * SLAB_ELEMS
               + (r & 127) * 40 + (kc & 31);
    *(uint2*)&oh[off] = h;
    *(uint2*)&ol[off] = l;
}

// ---------------------------------------------------------------------------
// GEMM on pre-split padded bf16 operands: Out[M,N] = A @ B^T + bias.
// bulk-DMA 2-stage pipeline (t0 orchestrates, mbarrier parity), wmma bf16x3
// mainloop identical to R9. 128x128x32 tile, 256 thr, 2 CTAs/SM.
// stage layout (bytes): Ah +0, Al +10240, Bh +20480, Bl +30720 (rows of 40)
// mode 0: fp32 out  1: norm+rope fp32 (Q)  2: norm+rope packed K  3: tf32 V
// ---------------------------------------------------------------------------
__global__ void __launch_bounds__(256, 2)
gemm_blk(const bf16* __restrict__ Ahg, const bf16* __restrict__ Alg,
         const bf16* __restrict__ Bhg, const bf16* __restrict__ Blg,
         const float* __restrict__ bias,
         float* __restrict__ Out,
         uint32_t* __restrict__ outW1, uint32_t* __restrict__ outW2,
         const float* __restrict__ normw, const float* __restrict__ rope,
         int mode)
{
    extern __shared__ char smemc[];
    __shared__ uint64_t s_mbar[2];

    const uint32_t sbase = smem_u32(smemc);
    const uint32_t mb0 = smem_u32(&s_mbar[0]);
    const uint32_t mb1 = smem_u32(&s_mbar[1]);

    const int t = threadIdx.x;
    const int warp = t >> 5;
    const int wr = warp >> 2;
    const int wc = warp & 3;
    const int m0 = blockIdx.y * 128;
    const int n0 = blockIdx.x * 128;
    const int hh = blockIdx.x;

    if (t == 0) { MBINIT(mb0, 1); MBINIT(mb1, 1); }
    __syncthreads();

    const bf16* pAh = Ahg + (size_t)(m0 >> 7) * TILE_ELEMS;
    const bf16* pAl = Alg + (size_t)(m0 >> 7) * TILE_ELEMS;
    const bf16* pBh = Bhg + (size_t)(n0 >> 7) * TILE_ELEMS;
    const bf16* pBl = Blg + (size_t)(n0 >> 7) * TILE_ELEMS;

    auto fill = [&](int s) {
        int st = s & 1;
        uint32_t fb = st ? mb1 : mb0;
        uint32_t d  = sbase + st * 40960;
        size_t o = (size_t)s * SLAB_ELEMS;
        MBEXPECT(fb, 40960u);
        BULKCP(d,         pAh + o, 10240u, fb);
        BULKCP(d + 10240, pAl + o, 10240u, fb);
        BULKCP(d + 20480, pBh + o, 10240u, fb);
        BULKCP(d + 30720, pBl + o, 10240u, fb);
    };

    if (t == 0) { fill(0); fill(1); }

    wmma::fragment<wmma::accumulator, 16, 16, 16, float> cfrag[4][2];
#pragma unroll
    for (int mi = 0; mi < 4; mi++)
#pragma unroll
        for (int nj = 0; nj < 2; nj++) wmma::fill_fragment(cfrag[mi][nj], 0.0f);

    for (int s = 0; s < 64; s++) {
        const int st = s & 1;
        const uint32_t ph = (uint32_t)((s >> 1) & 1);
        MBWAIT(st ? mb1 : mb0, ph);

        bf16* Ash = (bf16*)(smemc + st * 40960);
        bf16* Asl = Ash + 5120;
        bf16* Bsh = Ash + 10240;
        bf16* Bsl = Ash + 15360;

#pragma unroll
        for (int ks = 0; ks < 2; ks++) {
            wmma::fragment<wmma::matrix_b, 16, 16, 16, bf16, wmma::col_major> bh[2], bl[2];
#pragma unroll
            for (int nj = 0; nj < 2; nj++) {
                wmma::load_matrix_sync(bh[nj], &Bsh[(wc * 32 + nj * 16) * 40 + ks * 16], 40);
                wmma::load_matrix_sync(bl[nj], &Bsl[(wc * 32 + nj * 16) * 40 + ks * 16], 40);
            }
#pragma unroll
            for (int mi = 0; mi < 4; mi++) {
                wmma::fragment<wmma::matrix_a, 16, 16, 16, bf16, wmma::row_major> ah, al;
                wmma::load_matrix_sync(ah, &Ash[(wr * 64 + mi * 16) * 40 + ks * 16], 40);
                wmma::load_matrix_sync(al, &Asl[(wr * 64 + mi * 16) * 40 + ks * 16], 40);
#pragma unroll
                for (int nj = 0; nj < 2; nj++) {
                    wmma::mma_sync(cfrag[mi][nj], al, bh[nj], cfrag[mi][nj]);
                    wmma::mma_sync(cfrag[mi][nj], ah, bl[nj], cfrag[mi][nj]);
                    wmma::mma_sync(cfrag[mi][nj], ah, bh[nj], cfrag[mi][nj]);
                }
            }
        }
        __syncthreads();                       // all consumed stage st
        if (t == 0 && s + 2 < 64) fill(s + 2); // refill the just-freed stage
    }

    // epilogue: stage to smem, then mode-specific output
    float* Cs = (float*)smemc;  // [128][132] = 67584 B <= 81920 B
#pragma unroll
    for (int mi = 0; mi < 4; mi++)
#pragma unroll
        for (int nj = 0; nj < 2; nj++)
            wmma::store_matrix_sync(&Cs[(wr * 64 + mi * 16) * 132 + wc * 32 + nj * 16],
                                    cfrag[mi][nj], 132, wmma::mem_row_major);
    __syncthreads();

    if (mode == 0) {
#pragma unroll
        for (int i = 0; i < 16; i++) {
            int idx = i * 256 + t;
            int r = idx >> 5, c4 = (idx & 31) * 4;
            float4 cv = *(float4*)&Cs[r * 132 + c4];
            float4 bb = *(const float4*)&bias[n0 + c4];
            cv.x += bb.x; cv.y += bb.y; cv.z += bb.z; cv.w += bb.w;
            *(float4*)&Out[(size_t)(m0 + r) * CC + n0 + c4] = cv;
        }
    } else if (mode == 3) {
#pragma unroll
        for (int i = 0; i < 16; i++) {
            int idx = i * 256 + t;
            int r = idx >> 5, c4 = (idx & 31) * 4;
            float4 cv = *(float4*)&Cs[r * 132 + c4];
            float4 bb = *(const float4*)&bias[n0 + c4];
            cv.x += bb.x; cv.y += bb.y; cv.z += bb.z; cv.w += bb.w;
            size_t base = ((size_t)(m0 + r) * HH + hh) * 128;
            float vals[4] = {cv.x, cv.y, cv.z, cv.w};
#pragma unroll
            for (int e = 0; e < 4; e++) {
                int d = c4 + e;
                int dp = (d & 7) * 16 + (d >> 3);
                outW1[base + dp] = f2tf32(vals[e]);
            }
        }
    } else {
        const int r = t >> 1, half = t & 1;
        const int s = m0 + r;
        float* row = &Cs[r * 132 + half * 64];
        const float* bias_h = &bias[n0 + half * 64];
        float ssq = 0.0f;
#pragma unroll
        for (int j = 0; j < 16; j++) {
            float4 c = ((float4*)row)[j];
            float4 bb = ((const float4*)bias_h)[j];
            c.x += bb.x; c.y += bb.y; c.z += bb.z; c.w += bb.w;
            ((float4*)row)[j] = c;
            ssq += c.x * c.x + c.y * c.y + c.z * c.z + c.w * c.w;
        }
        ssq += __shfl_xor_sync(0xffffffffu, ssq, 1);
        float inv = rsqrtf(ssq * (1.0f / 128.0f) + EPSF);
        const float* wv = &normw[half * 64];
        const float* rp = &rope[(size_t)s * 256 + half * 128];
        float* outp = &Out[(size_t)(m0 + r) * CC + n0 + half * 64];
#pragma unroll
        for (int j = 0; j < 16; j++) {
            float4 c = ((float4*)row)[j];
            float4 ww = ((const float4*)wv)[j];
            float x0 = c.x * inv * ww.x;
            float x1 = c.y * inv * ww.y;
            float x2 = c.z * inv * ww.z;
            float x3 = c.w * inv * ww.w;
            float4 rA = ((const float4*)rp)[2 * j];
            float4 rB = ((const float4*)rp)[2 * j + 1];
            float4 ov;
            ov.x = rA.x * x0 + rA.y * x1;
            ov.y = rA.z * x0 + rA.w * x1;
            ov.z = rB.x * x2 + rB.y * x3;
            ov.w = rB.z * x2 + rB.w * x3;
            if (mode == 1) {
                ((float4*)outp)[j] = ov;
            } else {
                size_t kb = ((size_t)s * HH + hh) * 64 + half * 32 + j * 2;
                uint2 wh = make_uint2(bfpack(ov.x, ov.y), bfpack(ov.z, ov.w));
                uint2 wl = make_uint2(bfpack(bfres(ov.x), bfres(ov.y)),
                                      bfpack(bfres(ov.z), bfres(ov.w)));
                *(uint2*)&outW1[kb] = wh;
                *(uint2*)&outW2[kb] = wl;
            }
        }
    }
}

// ---------------------------------------------------------------------------
// Flash attention (unchanged from R9): cp.async double-buffered K/V,
// ldmatrix QK (bf16x3), vectorized PV (1xTF32).
// ---------------------------------------------------------------------------
__global__ void __launch_bounds__(256, 1)
flash_attn_tc(const float* __restrict__ q,
              const uint32_t* __restrict__ kh,
              const uint32_t* __restrict__ kl,
              const uint32_t* __restrict__ vv,
              float* __restrict__ o)
{
    extern __shared__ uint32_t usm[];
    uint32_t sbase = smem_u32(usm);

    const int h  = blockIdx.y;
    const int q0 = blockIdx.x * 128;
    const int t  = threadIdx.x;
    const int warp = t >> 5;
    const int lane = t & 31;
    const int g   = lane >> 2;
    const int tig = lane & 3;
    const int r0 = warp * 16 + g;
    const int r1 = r0 + 8;
    const float scale = 0.08838834764831845f;

    uint32_t* Ps = usm + 34304;

    const int rowsel = (lane & 7) + ((lane >> 4) & 1) * 8;
    const int halfw  = ((lane >> 3) & 1) * 4;

    uint32_t qh[8][4], ql[8][4];
    {
        const float* qr0 = &q[((size_t)(q0 + r0) * HH + h) * DD];
        const float* qr1 = &q[((size_t)(q0 + r1) * HH + h) * DD];
#pragma unroll
        for (int ks = 0; ks < 8; ks++) {
            int c = ks * 16 + 2 * tig;
            float a0 = qr0[c] * scale,     a1 = qr0[c + 1] * scale;
            float b0 = qr1[c] * scale,     b1 = qr1[c + 1] * scale;
            float c0 = qr0[c + 8] * scale, c1 = qr0[c + 9] * scale;
            float d0 = qr1[c + 8] * scale, d1 = qr1[c + 9] * scale;
            qh[ks][0] = bfpack(a0, a1);
            qh[ks][1] = bfpack(b0, b1);
            qh[ks][2] = bfpack(c0, c1);
            qh[ks][3] = bfpack(d0, d1);
            ql[ks][0] = bfpack(bfres(a0), bfres(a1));
            ql[ks][1] = bfpack(bfres(b0), bfres(b1));
            ql[ks][2] = bfpack(bfres(c0), bfres(c1));
            ql[ks][3] = bfpack(bfres(d0), bfres(d1));
        }
    }

    float m0r = -1e30f, m1r = -1e30f, l0 = 0.0f, l1 = 0.0f;
    float oacc[16][4];
#pragma unroll
    for (int j = 0; j < 16; j++)
#pragma unroll
        for (int e = 0; e < 4; e++) oacc[j][e] = 0.0f;

    auto fill = [&](int st, int kv) {
        const uint32_t dKH = sbase + (st * 4352) * 4;
        const uint32_t dKL = sbase + (8704 + st * 4352) * 4;
        const uint32_t dV  = sbase + (17408 + st * 8448) * 4;
#pragma unroll
        for (int i = 0; i < 4; i++) {
            int c = i * 256 + t; int r = c >> 4, w = (c & 15) * 4;
            CP16(dKH + (uint32_t)(r * 68 + w) * 4,
                 &kh[((size_t)(kv + r) * HH + h) * 64 + w]);
        }
#pragma unroll
        for (int i = 0; i < 4; i++) {
            int c = i * 256 + t; int r = c >> 4, w = (c & 15) * 4;
            CP16(dKL + (uint32_t)(r * 68 + w) * 4,
                 &kl[((size_t)(kv + r) * HH + h) * 64 + w]);
        }
#pragma unroll
        for (int i = 0; i < 8; i++) {
            int c = i * 256 + t; int r = c >> 5, w = (c & 31) * 4;
            CP16(dV + (uint32_t)(r * 132 + w) * 4,
                 &vv[((size_t)(kv + r) * HH + h) * 128 + w]);
        }
    };

    fill(0, 0);
    CP_COMMIT();

    for (int kv0 = 0; kv0 < SS; kv0 += 64) {
        const int st = (kv0 >> 6) & 1;
        const bool more = (kv0 + 64) < SS;

        if (more) { fill(st ^ 1, kv0 + 64); CP_COMMIT(); }

        if (more) { asm volatile("cp.async.wait_group 1;" ::: "memory"); }
        else      { asm volatile("cp.async.wait_group 0;" ::: "memory"); }
        __syncthreads();

        const uint32_t bKH = sbase + (st * 4352) * 4;
        const uint32_t bKL = sbase + (8704 + st * 4352) * 4;
        uint32_t* VsSt = usm + 17408 + st * 8448;

        float sacc[8][4];
#pragma unroll
        for (int j = 0; j < 8; j++)
#pragma unroll
            for (int e = 0; e < 4; e++) sacc[j][e] = 0.0f;

#pragma unroll
        for (int ks = 0; ks < 8; ks++) {
#pragma unroll
            for (int jp = 0; jp < 4; jp++) {
                uint32_t woff = (uint32_t)((jp * 16 + rowsel) * 68 + ks * 8 + halfw) * 4;
                uint32_t h0, h1, h2, h3, l0r, l1r, l2r, l3r;
                ldsm_x4(bKH + woff, h0, h1, h2, h3);
                ldsm_x4(bKL + woff, l0r, l1r, l2r, l3r);
                mma16(sacc[2 * jp],     ql[ks], h0, h1);
                mma16(sacc[2 * jp],     qh[ks], l0r, l1r);
                mma16(sacc[2 * jp],     qh[ks], h0, h1);
                mma16(sacc[2 * jp + 1], ql[ks], h2, h3);
                mma16(sacc[2 * jp + 1], qh[ks], l2r, l3r);
                mma16(sacc[2 * jp + 1], qh[ks], h2, h3);
            }
        }

        float rmax0 = -1e30f, rmax1 = -1e30f;
#pragma unroll
        for (int j = 0; j < 8; j++) {
            rmax0 = fmaxf(rmax0, fmaxf(sacc[j][0], sacc[j][1]));
            rmax1 = fmaxf(rmax1, fmaxf(sacc[j][2], sacc[j][3]));
        }
#pragma unroll
        for (int off = 1; off < 4; off <<= 1) {
            rmax0 = fmaxf(rmax0, __shfl_xor_sync(0xffffffffu, rmax0, off));
            rmax1 = fmaxf(rmax1, __shfl_xor_sync(0xffffffffu, rmax1, off));
        }
        float mn0 = fmaxf(m0r, rmax0);
        float mn1 = fmaxf(m1r, rmax1);
        float cr0 = __expf(m0r - mn0);
        float cr1 = __expf(m1r - mn1);
        float rs0 = 0.0f, rs1 = 0.0f;
#pragma unroll
        for (int j = 0; j < 8; j++) {
            float e0 = __expf(sacc[j][0] - mn0);
            float e1 = __expf(sacc[j][1] - mn0);
            float e2 = __expf(sacc[j][2] - mn1);
            float e3 = __expf(sacc[j][3] - mn1);
            rs0 += e0 + e1;
            rs1 += e2 + e3;
            int col = j * 8 + 2 * tig;
            Ps[r0 * 68 + col]     = f2tf32(e0);
            Ps[r0 * 68 + col + 1] = f2tf32(e1);
            Ps[r1 * 68 + col]     = f2tf32(e2);
            Ps[r1 * 68 + col + 1] = f2tf32(e3);
        }
#pragma unroll
        for (int off = 1; off < 4; off <<= 1) {
            rs0 += __shfl_xor_sync(0xffffffffu, rs0, off);
            rs1 += __shfl_xor_sync(0xffffffffu, rs1, off);
        }
        l0 = l0 * cr0 + rs0;
        l1 = l1 * cr1 + rs1;
        m0r = mn0;
        m1r = mn1;
#pragma unroll
        for (int j = 0; j < 16; j++) {
            oacc[j][0] *= cr0; oacc[j][1] *= cr0;
            oacc[j][2] *= cr1; oacc[j][3] *= cr1;
        }
        __syncwarp();

#pragma unroll
        for (int kc = 0; kc < 8; kc++) {
            uint32_t a[4];
            a[0] = Ps[r0 * 68 + kc * 8 + tig];
            a[1] = Ps[r1 * 68 + kc * 8 + tig];
            a[2] = Ps[r0 * 68 + kc * 8 + tig + 4];
            a[3] = Ps[r1 * 68 + kc * 8 + tig + 4];
            const int row0 = kc * 8 + tig, row1 = row0 + 4;
            uint32_t vb0[16], vb1[16];
#pragma unroll
            for (int jq = 0; jq < 4; jq++) {
                *(uint4*)&vb0[jq * 4] = *(uint4*)&VsSt[row0 * 132 + g * 16 + jq * 4];
                *(uint4*)&vb1[jq * 4] = *(uint4*)&VsSt[row1 * 132 + g * 16 + jq * 4];
            }
#pragma unroll
            for (int j = 0; j < 16; j++)
                mma8(oacc[j], a, vb0[j], vb1[j]);
        }
        __syncthreads();
    }

    float inv0 = 1.0f / l0, inv1 = 1.0f / l1;
    float* o0 = &o[((size_t)(q0 + r0) * HH + h) * DD];
    float* o1 = &o[((size_t)(q0 + r1) * HH + h) * DD];
#pragma unroll
    for (int j = 0; j < 16; j++) {
        int col = j * 8 + 2 * tig;
        float2 s0 = make_float2(oacc[j][0] * inv0, oacc[j][1] * inv0);
        float2 s1 = make_float2(oacc[j][2] * inv1, oacc[j][3] * inv1);
        *(float2*)&o0[col] = s0;
        *(float2*)&o1[col] = s1;
    }
}

// ---------------------------------------------------------------------------
extern "C" void kernel_launch(void* const* d_in, const int* in_sizes, int n_in,
                              void* d_out, int out_size)
{
    const float* x    = (const float*)d_in[0];
    const float* rope = (const float*)d_in[1];
    const float* Wq   = (const float*)d_in[2];
    const float* bq   = (const float*)d_in[3];
    const float* Wk   = (const float*)d_in[4];
    const float* bk   = (const float*)d_in[5];
    const float* Wv   = (const float*)d_in[6];
    const float* bv   = (const float*)d_in[7];
    const float* qn_w = (const float*)d_in[8];
    const float* kn_w = (const float*)d_in[9];
    const float* Wo   = (const float*)d_in[10];
    const float* bo   = (const float*)d_in[11];
    float* out = (float*)d_out;

    float *qp, *ap;
    uint32_t *khp, *klp, *vp;
    bf16 *xh, *xl, *ah, *al;
    bf16 *wqh, *wql, *wkh, *wkl, *wvh, *wvl, *woh, *wol;
    cudaGetSymbolAddress((void**)&qp,  g_q);
    cudaGetSymbolAddress((void**)&khp, g_kh);
    cudaGetSymbolAddress((void**)&klp, g_kl);
    cudaGetSymbolAddress((void**)&vp,  g_v);
    cudaGetSymbolAddress((void**)&ap,  g_attn);
    cudaGetSymbolAddress((void**)&xh,  g_xh);
    cudaGetSymbolAddress((void**)&xl,  g_xl);
    cudaGetSymbolAddress((void**)&ah,  g_ah);
    cudaGetSymbolAddress((void**)&al,  g_al);
    cudaGetSymbolAddress((void**)&wqh, g_wqh);
    cudaGetSymbolAddress((void**)&wql, g_wql);
    cudaGetSymbolAddress((void**)&wkh, g_wkh);
    cudaGetSymbolAddress((void**)&wkl, g_wkl);
    cudaGetSymbolAddress((void**)&wvh, g_wvh);
    cudaGetSymbolAddress((void**)&wvl, g_wvl);
    cudaGetSymbolAddress((void**)&woh, g_woh);
    cudaGetSymbolAddress((void**)&wol, g_wol);

    const int smem_gemm = 81920;             // 2 x 40960 stages (Cs aliases)
    const int smem_attn = 172032;
    cudaFuncSetAttribute(gemm_blk, cudaFuncAttributeMaxDynamicSharedMemorySize,
                         smem_gemm);
    cudaFuncSetAttribute(flash_attn_tc, cudaFuncAttributeMaxDynamicSharedMemorySize,
                         smem_attn);

    split_sw<<<8192, 256>>>(x,  xh,  xl);    // 4096 x 2048
    split_sw<<<4096, 256>>>(Wq, wqh, wql);   // 2048 x 2048
    split_sw<<<4096, 256>>>(Wk, wkh, wkl);
    split_sw<<<4096, 256>>>(Wv, wvh, wvl);
    split_sw<<<4096, 256>>>(Wo, woh, wol);

    dim3 ggrid(CC / 128, SS / 128);
    gemm_blk<<<ggrid, 256, smem_gemm>>>(xh, xl, wqh, wql, bq, qp, nullptr, nullptr,
                                        qn_w, rope, 1);
    gemm_blk<<<ggrid, 256, smem_gemm>>>(xh, xl, wkh, wkl, bk, nullptr, khp, klp,
                                        kn_w, rope, 2);
    gemm_blk<<<ggrid, 256, smem_gemm>>>(xh, xl, wvh, wvl, bv, nullptr, vp, nullptr,
                                        nullptr, nullptr, 3);

    dim3 agrid(SS / 128, HH);
    flash_attn_tc<<<agrid, 256, smem_attn>>>(qp, khp, klp, vp, ap);

    split_sw<<<8192, 256>>>(ap, ah, al);
    gemm_blk<<<ggrid, 256, smem_gemm>>>(ah, al, woh, wol, bo, out, nullptr, nullptr,
                                        nullptr, nullptr, 0);
}

// round 14
// speedup vs baseline: 3.5533x; 1.1187x over previous
#include <cuda_runtime.h>
#include <cstdint>
#include <cuda_bf16.h>
#include <cuda_fp16.h>
#include <mma.h>
#include <math.h>

using namespace nvcuda;

#define SS 4096
#define CC 2048
#define HH 16
#define DD 128
#define EPSF 1.1920929e-07f

typedef __nv_bfloat16 bf16;

// Scratch (no cudaMalloc allowed)
__device__ float    g_q[SS * CC];            // Q fp32 (post norm+rope)
__device__ uint32_t g_kh[SS * HH * 64];      // K hi, packed bf16x2 (d pairs)
__device__ uint32_t g_kl[SS * HH * 64];      // K lo, packed bf16x2
__device__ uint32_t g_v[SS * HH * 64];       // V fp16 k-pair words [s/2][H][128]
// pre-split bf16 hi/lo operands in PADDED TILE-IMAGE layout:
// [tile=row/128][slab=k/32][128 rows x 40 bf16 = 10240 B]
#define PADN(r, c) ((size_t)(r) * (c) * 5 / 4)
__device__ bf16 g_xh[PADN(SS, CC)],  g_xl[PADN(SS, CC)];
__device__ bf16 g_ah[PADN(SS, CC)],  g_al[PADN(SS, CC)];
__device__ bf16 g_wqh[PADN(CC, CC)], g_wql[PADN(CC, CC)];
__device__ bf16 g_wkh[PADN(CC, CC)], g_wkl[PADN(CC, CC)];
__device__ bf16 g_wvh[PADN(CC, CC)], g_wvl[PADN(CC, CC)];
__device__ bf16 g_woh[PADN(CC, CC)], g_wol[PADN(CC, CC)];

#define TILE_ELEMS 327680u    // 64 slabs * 5120 elems
#define SLAB_ELEMS 5120u      // 128 rows * 40 bf16

// ---------------------------------------------------------------------------
// helpers
// ---------------------------------------------------------------------------
__device__ __forceinline__ uint32_t bfpack(float x, float y) {
    __nv_bfloat162 h = __floats2bfloat162_rn(x, y);
    return *(uint32_t*)&h;
}
__device__ __forceinline__ float bfres(float x) {
    return x - __bfloat162float(__float2bfloat16_rn(x));
}
__device__ __forceinline__ uint32_t h2pack(float x, float y) {
    __half2 h = __floats2half2_rn(x, y);
    return *(uint32_t*)&h;
}

// bf16 m16n8k16 (QK)
__device__ __forceinline__ void mma16(float* c, const uint32_t* a,
                                      uint32_t b0, uint32_t b1) {
    asm volatile(
        "mma.sync.aligned.m16n8k16.row.col.f32.bf16.bf16.f32 "
        "{%0,%1,%2,%3}, {%4,%5,%6,%7}, {%8,%9}, {%0,%1,%2,%3};\n"
        : "+f"(c[0]), "+f"(c[1]), "+f"(c[2]), "+f"(c[3])
        : "r"(a[0]), "r"(a[1]), "r"(a[2]), "r"(a[3]), "r"(b0), "r"(b1));
}
// fp16 m16n8k16 (PV) — fp16 has 11-bit significand, same as tf32
__device__ __forceinline__ void mma16h(float* c, const uint32_t* a,
                                       uint32_t b0, uint32_t b1) {
    asm volatile(
        "mma.sync.aligned.m16n8k16.row.col.f32.f16.f16.f32 "
        "{%0,%1,%2,%3}, {%4,%5,%6,%7}, {%8,%9}, {%0,%1,%2,%3};\n"
        : "+f"(c[0]), "+f"(c[1]), "+f"(c[2]), "+f"(c[3])
        : "r"(a[0]), "r"(a[1]), "r"(a[2]), "r"(a[3]), "r"(b0), "r"(b1));
}

#define CP16(dst_u32, src_ptr) \
    asm volatile("cp.async.cg.shared.global [%0], [%1], 16;" \
                 :: "r"(dst_u32), "l"(src_ptr) : "memory")
#define CP_COMMIT() asm volatile("cp.async.commit_group;" ::: "memory")

__device__ __forceinline__ void ldsm_x4(uint32_t addr, uint32_t& r0, uint32_t& r1,
                                        uint32_t& r2, uint32_t& r3) {
    asm volatile("ldmatrix.sync.aligned.m8n8.x4.shared.b16 {%0,%1,%2,%3}, [%4];"
                 : "=r"(r0), "=r"(r1), "=r"(r2), "=r"(r3) : "r"(addr));
}

__device__ __forceinline__ uint32_t smem_u32(const void* p) {
    uint32_t a;
    asm("{ .reg .u64 tt; cvta.to.shared.u64 tt, %1; cvt.u32.u64 %0, tt; }"
        : "=r"(a) : "l"(p));
    return a;
}

// --- mbarrier + bulk-DMA primitives ---
#define MBINIT(m, c) \
    asm volatile("mbarrier.init.shared.b64 [%0], %1;" :: "r"(m), "r"(c) : "memory")
#define MBEXPECT(m, b) \
    asm volatile("mbarrier.arrive.expect_tx.shared.b64 _, [%0], %1;" :: "r"(m), "r"(b) : "memory")
#define BULKCP(dst, src, bytes, mbar) \
    asm volatile("cp.async.bulk.shared::cta.global.mbarrier::complete_tx::bytes [%0], [%1], %2, [%3];" \
                 :: "r"(dst), "l"(src), "r"(bytes), "r"(mbar) : "memory")

#define MBWAIT(mbar_addr, parity) do { \
    uint32_t _m = (mbar_addr), _p = (parity), _d; \
    asm volatile( \
        "{\n\t.reg .pred p;\n\t" \
        "mbarrier.try_wait.parity.acquire.cta.shared::cta.b64 p, [%1], %2;\n\t" \
        "selp.b32 %0, 1, 0, p;\n\t}" \
        : "=r"(_d) : "r"(_m), "r"(_p) : "memory"); \
    if (!_d) { \
        asm volatile( \
            "{\n\t.reg .pred P1;\n\t" \
            "WL_%=:\n\t" \
            "mbarrier.try_wait.parity.acquire.cta.shared::cta.b64 P1, [%0], %1, 0x989680;\n\t" \
            "@P1 bra.uni WD_%=;\n\t" \
            "bra.uni WL_%=;\n\t" \
            "WD_%=:\n\t}" \
            :: "r"(_m), "r"(_p) : "memory"); \
    } \
} while (0)

// ---------------------------------------------------------------------------
// split fp32 -> bf16 hi/lo in padded tile-image layout (rows x 2048 K cols)
// ---------------------------------------------------------------------------
__global__ void split_sw(const float* __restrict__ in,
                         bf16* __restrict__ oh, bf16* __restrict__ ol)
{
    int idx = blockIdx.x * 256 + threadIdx.x;
    int r  = idx >> 9;
    int kc = (idx & 511) * 4;
    float4 v = *(const float4*)&in[(size_t)r * 2048 + kc];
    uint2 h = make_uint2(bfpack(v.x, v.y), bfpack(v.z, v.w));
    uint2 l = make_uint2(bfpack(bfres(v.x), bfres(v.y)),
                         bfpack(bfres(v.z), bfres(v.w)));
    size_t off = (size_t)(r >> 7) * TILE_ELEMS + (size_t)(kc >> 5) * SLAB_ELEMS
               + (r & 127) * 40 + (kc & 31);
    *(uint2*)&oh[off] = h;
    *(uint2*)&ol[off] = l;
}

// ---------------------------------------------------------------------------
// GEMM (unchanged mainloop from R11): bulk-DMA 2-stage, wmma bf16x3.
// mode 0: pre-split bf16 hi/lo tile-image out is NOT used here (flash does it)
//         -> mode 0 = plain fp32 out (final projection)
// mode 1: norm+rope fp32 (Q)   mode 2: norm+rope packed K   mode 3: fp16 V pairs
// ---------------------------------------------------------------------------
__global__ void __launch_bounds__(256, 2)
gemm_blk(const bf16* __restrict__ Ahg, const bf16* __restrict__ Alg,
         const bf16* __restrict__ Bhg, const bf16* __restrict__ Blg,
         const float* __restrict__ bias,
         float* __restrict__ Out,
         uint32_t* __restrict__ outW1, uint32_t* __restrict__ outW2,
         const float* __restrict__ normw, const float* __restrict__ rope,
         int mode)
{
    extern __shared__ char smemc[];
    __shared__ uint64_t s_mbar[2];

    const uint32_t sbase = smem_u32(smemc);
    const uint32_t mb0 = smem_u32(&s_mbar[0]);
    const uint32_t mb1 = smem_u32(&s_mbar[1]);

    const int t = threadIdx.x;
    const int warp = t >> 5;
    const int wr = warp >> 2;
    const int wc = warp & 3;
    const int m0 = blockIdx.y * 128;
    const int n0 = blockIdx.x * 128;
    const int hh = blockIdx.x;

    if (t == 0) { MBINIT(mb0, 1); MBINIT(mb1, 1); }
    __syncthreads();

    const bf16* pAh = Ahg + (size_t)(m0 >> 7) * TILE_ELEMS;
    const bf16* pAl = Alg + (size_t)(m0 >> 7) * TILE_ELEMS;
    const bf16* pBh = Bhg + (size_t)(n0 >> 7) * TILE_ELEMS;
    const bf16* pBl = Blg + (size_t)(n0 >> 7) * TILE_ELEMS;

    auto fill = [&](int s) {
        int st = s & 1;
        uint32_t fb = st ? mb1 : mb0;
        uint32_t d  = sbase + st * 40960;
        size_t o = (size_t)s * SLAB_ELEMS;
        MBEXPECT(fb, 40960u);
        BULKCP(d,         pAh + o, 10240u, fb);
        BULKCP(d + 10240, pAl + o, 10240u, fb);
        BULKCP(d + 20480, pBh + o, 10240u, fb);
        BULKCP(d + 30720, pBl + o, 10240u, fb);
    };

    if (t == 0) { fill(0); fill(1); }

    wmma::fragment<wmma::accumulator, 16, 16, 16, float> cfrag[4][2];
#pragma unroll
    for (int mi = 0; mi < 4; mi++)
#pragma unroll
        for (int nj = 0; nj < 2; nj++) wmma::fill_fragment(cfrag[mi][nj], 0.0f);

    for (int s = 0; s < 64; s++) {
        const int st = s & 1;
        const uint32_t ph = (uint32_t)((s >> 1) & 1);
        MBWAIT(st ? mb1 : mb0, ph);

        bf16* Ash = (bf16*)(smemc + st * 40960);
        bf16* Asl = Ash + 5120;
        bf16* Bsh = Ash + 10240;
        bf16* Bsl = Ash + 15360;

#pragma unroll
        for (int ks = 0; ks < 2; ks++) {
            wmma::fragment<wmma::matrix_b, 16, 16, 16, bf16, wmma::col_major> bh[2], bl[2];
#pragma unroll
            for (int nj = 0; nj < 2; nj++) {
                wmma::load_matrix_sync(bh[nj], &Bsh[(wc * 32 + nj * 16) * 40 + ks * 16], 40);
                wmma::load_matrix_sync(bl[nj], &Bsl[(wc * 32 + nj * 16) * 40 + ks * 16], 40);
            }
#pragma unroll
            for (int mi = 0; mi < 4; mi++) {
                wmma::fragment<wmma::matrix_a, 16, 16, 16, bf16, wmma::row_major> ah, al;
                wmma::load_matrix_sync(ah, &Ash[(wr * 64 + mi * 16) * 40 + ks * 16], 40);
                wmma::load_matrix_sync(al, &Asl[(wr * 64 + mi * 16) * 40 + ks * 16], 40);
#pragma unroll
                for (int nj = 0; nj < 2; nj++) {
                    wmma::mma_sync(cfrag[mi][nj], al, bh[nj], cfrag[mi][nj]);
                    wmma::mma_sync(cfrag[mi][nj], ah, bl[nj], cfrag[mi][nj]);
                    wmma::mma_sync(cfrag[mi][nj], ah, bh[nj], cfrag[mi][nj]);
                }
            }
        }
        __syncthreads();
        if (t == 0 && s + 2 < 64) fill(s + 2);
    }

    float* Cs = (float*)smemc;  // [128][132]
#pragma unroll
    for (int mi = 0; mi < 4; mi++)
#pragma unroll
        for (int nj = 0; nj < 2; nj++)
            wmma::store_matrix_sync(&Cs[(wr * 64 + mi * 16) * 132 + wc * 32 + nj * 16],
                                    cfrag[mi][nj], 132, wmma::mem_row_major);
    __syncthreads();

    if (mode == 0) {
#pragma unroll
        for (int i = 0; i < 16; i++) {
            int idx = i * 256 + t;
            int r = idx >> 5, c4 = (idx & 31) * 4;
            float4 cv = *(float4*)&Cs[r * 132 + c4];
            float4 bb = *(const float4*)&bias[n0 + c4];
            cv.x += bb.x; cv.y += bb.y; cv.z += bb.z; cv.w += bb.w;
            *(float4*)&Out[(size_t)(m0 + r) * CC + n0 + c4] = cv;
        }
    } else if (mode == 3) {
        // V: fp16 halves packed as k-pairs (s even -> low half); d interleaved
        __half* vh = (__half*)outW1;
#pragma unroll
        for (int i = 0; i < 16; i++) {
            int idx = i * 256 + t;
            int r = idx >> 5, c4 = (idx & 31) * 4;
            float4 cv = *(float4*)&Cs[r * 132 + c4];
            float4 bb = *(const float4*)&bias[n0 + c4];
            cv.x += bb.x; cv.y += bb.y; cv.z += bb.z; cv.w += bb.w;
            int sidx = m0 + r;
            size_t wb = ((size_t)(sidx >> 1) * HH + hh) * 128;
            float vals[4] = {cv.x, cv.y, cv.z, cv.w};
#pragma unroll
            for (int e = 0; e < 4; e++) {
                int d = c4 + e;
                int dp = (d & 7) * 16 + (d >> 3);
                vh[(wb + dp) * 2 + (sidx & 1)] = __float2half_rn(vals[e]);
            }
        }
    } else {
        const int r = t >> 1, half = t & 1;
        const int s = m0 + r;
        float* row = &Cs[r * 132 + half * 64];
        const float* bias_h = &bias[n0 + half * 64];
        float ssq = 0.0f;
#pragma unroll
        for (int j = 0; j < 16; j++) {
            float4 c = ((float4*)row)[j];
            float4 bb = ((const float4*)bias_h)[j];
            c.x += bb.x; c.y += bb.y; c.z += bb.z; c.w += bb.w;
            ((float4*)row)[j] = c;
            ssq += c.x * c.x + c.y * c.y + c.z * c.z + c.w * c.w;
        }
        ssq += __shfl_xor_sync(0xffffffffu, ssq, 1);
        float inv = rsqrtf(ssq * (1.0f / 128.0f) + EPSF);
        const float* wv = &normw[half * 64];
        const float* rp = &rope[(size_t)s * 256 + half * 128];
        float* outp = &Out[(size_t)(m0 + r) * CC + n0 + half * 64];
#pragma unroll
        for (int j = 0; j < 16; j++) {
            float4 c = ((float4*)row)[j];
            float4 ww = ((const float4*)wv)[j];
            float x0 = c.x * inv * ww.x;
            float x1 = c.y * inv * ww.y;
            float x2 = c.z * inv * ww.z;
            float x3 = c.w * inv * ww.w;
            float4 rA = ((const float4*)rp)[2 * j];
            float4 rB = ((const float4*)rp)[2 * j + 1];
            float4 ov;
            ov.x = rA.x * x0 + rA.y * x1;
            ov.y = rA.z * x0 + rA.w * x1;
            ov.z = rB.x * x2 + rB.y * x3;
            ov.w = rB.z * x2 + rB.w * x3;
            if (mode == 1) {
                ((float4*)outp)[j] = ov;
            } else {
                size_t kb = ((size_t)s * HH + hh) * 64 + half * 32 + j * 2;
                uint2 wh = make_uint2(bfpack(ov.x, ov.y), bfpack(ov.z, ov.w));
                uint2 wl = make_uint2(bfpack(bfres(ov.x), bfres(ov.y)),
                                      bfpack(bfres(ov.z), bfres(ov.w)));
                *(uint2*)&outW1[kb] = wh;
                *(uint2*)&outW2[kb] = wl;
            }
        }
    }
}

// ---------------------------------------------------------------------------
// Flash attention: QK bf16x3 (ldmatrix), PV fp16 m16n8k16, output written
// directly as pre-split bf16 hi/lo in GEMM tile-image layout.
// smem words: KsH st*4352 [64][68]; KsL 8704+st*4352; Vs 17408+st*4224 [32][132];
// Ps 25856 [128][36]. Total 30464 w = 121856 B.
// ---------------------------------------------------------------------------
__global__ void __launch_bounds__(256, 1)
flash_attn_tc(const float* __restrict__ q,
              const uint32_t* __restrict__ kh,
              const uint32_t* __restrict__ kl,
              const uint32_t* __restrict__ vv,
              bf16* __restrict__ oh, bf16* __restrict__ ol)
{
    extern __shared__ uint32_t usm[];
    uint32_t sbase = smem_u32(usm);

    const int h  = blockIdx.y;
    const int q0 = blockIdx.x * 128;
    const int t  = threadIdx.x;
    const int warp = t >> 5;
    const int lane = t & 31;
    const int g   = lane >> 2;
    const int tig = lane & 3;
    const int r0 = warp * 16 + g;
    const int r1 = r0 + 8;
    const float scale = 0.08838834764831845f;

    uint32_t* Ps = usm + 25856;

    const int rowsel = (lane & 7) + ((lane >> 4) & 1) * 8;
    const int halfw  = ((lane >> 3) & 1) * 4;

    uint32_t qh[8][4], ql[8][4];
    {
        const float* qr0 = &q[((size_t)(q0 + r0) * HH + h) * DD];
        const float* qr1 = &q[((size_t)(q0 + r1) * HH + h) * DD];
#pragma unroll
        for (int ks = 0; ks < 8; ks++) {
            int c = ks * 16 + 2 * tig;
            float a0 = qr0[c] * scale,     a1 = qr0[c + 1] * scale;
            float b0 = qr1[c] * scale,     b1 = qr1[c + 1] * scale;
            float c0 = qr0[c + 8] * scale, c1 = qr0[c + 9] * scale;
            float d0 = qr1[c + 8] * scale, d1 = qr1[c + 9] * scale;
            qh[ks][0] = bfpack(a0, a1);
            qh[ks][1] = bfpack(b0, b1);
            qh[ks][2] = bfpack(c0, c1);
            qh[ks][3] = bfpack(d0, d1);
            ql[ks][0] = bfpack(bfres(a0), bfres(a1));
            ql[ks][1] = bfpack(bfres(b0), bfres(b1));
            ql[ks][2] = bfpack(bfres(c0), bfres(c1));
            ql[ks][3] = bfpack(bfres(d0), bfres(d1));
        }
    }

    float m0r = -1e30f, m1r = -1e30f, l0 = 0.0f, l1 = 0.0f;
    float oacc[16][4];
#pragma unroll
    for (int j = 0; j < 16; j++)
#pragma unroll
        for (int e = 0; e < 4; e++) oacc[j][e] = 0.0f;

    auto fill = [&](int st, int kv) {
        const uint32_t dKH = sbase + (st * 4352) * 4;
        const uint32_t dKL = sbase + (8704 + st * 4352) * 4;
        const uint32_t dV  = sbase + (17408 + st * 4224) * 4;
#pragma unroll
        for (int i = 0; i < 4; i++) {
            int c = i * 256 + t; int r = c >> 4, w = (c & 15) * 4;
            CP16(dKH + (uint32_t)(r * 68 + w) * 4,
                 &kh[((size_t)(kv + r) * HH + h) * 64 + w]);
        }
#pragma unroll
        for (int i = 0; i < 4; i++) {
            int c = i * 256 + t; int r = c >> 4, w = (c & 15) * 4;
            CP16(dKL + (uint32_t)(r * 68 + w) * 4,
                 &kl[((size_t)(kv + r) * HH + h) * 64 + w]);
        }
        // V: 32 pair-rows x 128 words
#pragma unroll
        for (int i = 0; i < 4; i++) {
            int c = i * 256 + t; int pr = c >> 5, w = (c & 31) * 4;
            CP16(dV + (uint32_t)(pr * 132 + w) * 4,
                 &vv[((size_t)((kv >> 1) + pr) * HH + h) * 128 + w]);
        }
    };

    fill(0, 0);
    CP_COMMIT();

    for (int kv0 = 0; kv0 < SS; kv0 += 64) {
        const int st = (kv0 >> 6) & 1;
        const bool more = (kv0 + 64) < SS;

        if (more) { fill(st ^ 1, kv0 + 64); CP_COMMIT(); }

        if (more) { asm volatile("cp.async.wait_group 1;" ::: "memory"); }
        else      { asm volatile("cp.async.wait_group 0;" ::: "memory"); }
        __syncthreads();

        const uint32_t bKH = sbase + (st * 4352) * 4;
        const uint32_t bKL = sbase + (8704 + st * 4352) * 4;
        uint32_t* VsSt = usm + 17408 + st * 4224;

        float sacc[8][4];
#pragma unroll
        for (int j = 0; j < 8; j++)
#pragma unroll
            for (int e = 0; e < 4; e++) sacc[j][e] = 0.0f;

#pragma unroll
        for (int ks = 0; ks < 8; ks++) {
#pragma unroll
            for (int jp = 0; jp < 4; jp++) {
                uint32_t woff = (uint32_t)((jp * 16 + rowsel) * 68 + ks * 8 + halfw) * 4;
                uint32_t h0, h1, h2, h3, l0r, l1r, l2r, l3r;
                ldsm_x4(bKH + woff, h0, h1, h2, h3);
                ldsm_x4(bKL + woff, l0r, l1r, l2r, l3r);
                mma16(sacc[2 * jp],     ql[ks], h0, h1);
                mma16(sacc[2 * jp],     qh[ks], l0r, l1r);
                mma16(sacc[2 * jp],     qh[ks], h0, h1);
                mma16(sacc[2 * jp + 1], ql[ks], h2, h3);
                mma16(sacc[2 * jp + 1], qh[ks], l2r, l3r);
                mma16(sacc[2 * jp + 1], qh[ks], h2, h3);
            }
        }

        float rmax0 = -1e30f, rmax1 = -1e30f;
#pragma unroll
        for (int j = 0; j < 8; j++) {
            rmax0 = fmaxf(rmax0, fmaxf(sacc[j][0], sacc[j][1]));
            rmax1 = fmaxf(rmax1, fmaxf(sacc[j][2], sacc[j][3]));
        }
#pragma unroll
        for (int off = 1; off < 4; off <<= 1) {
            rmax0 = fmaxf(rmax0, __shfl_xor_sync(0xffffffffu, rmax0, off));
            rmax1 = fmaxf(rmax1, __shfl_xor_sync(0xffffffffu, rmax1, off));
        }
        float mn0 = fmaxf(m0r, rmax0);
        float mn1 = fmaxf(m1r, rmax1);
        float cr0 = __expf(m0r - mn0);
        float cr1 = __expf(m1r - mn1);
        float rs0 = 0.0f, rs1 = 0.0f;
#pragma unroll
        for (int j = 0; j < 8; j++) {
            float e0 = __expf(sacc[j][0] - mn0);
            float e1 = __expf(sacc[j][1] - mn0);
            float e2 = __expf(sacc[j][2] - mn1);
            float e3 = __expf(sacc[j][3] - mn1);
            rs0 += e0 + e1;
            rs1 += e2 + e3;
            int wcol = j * 4 + tig;           // half2 pair word (cols j*8+2tig, +1)
            Ps[r0 * 36 + wcol] = h2pack(e0, e1);
            Ps[r1 * 36 + wcol] = h2pack(e2, e3);
        }
#pragma unroll
        for (int off = 1; off < 4; off <<= 1) {
            rs0 += __shfl_xor_sync(0xffffffffu, rs0, off);
            rs1 += __shfl_xor_sync(0xffffffffu, rs1, off);
        }
        l0 = l0 * cr0 + rs0;
        l1 = l1 * cr1 + rs1;
        m0r = mn0;
        m1r = mn1;
#pragma unroll
        for (int j = 0; j < 16; j++) {
            oacc[j][0] *= cr0; oacc[j][1] *= cr0;
            oacc[j][2] *= cr1; oacc[j][3] *= cr1;
        }
        __syncwarp();   // Ps rows r0/r1 warp-private

        // ---- PV: fp16 m16n8k16, k=64 -> 4 k-steps ----
#pragma unroll
        for (int kc = 0; kc < 4; kc++) {
            uint32_t a[4];
            a[0] = Ps[r0 * 36 + kc * 8 + tig];
            a[1] = Ps[r1 * 36 + kc * 8 + tig];
            a[2] = Ps[r0 * 36 + kc * 8 + 4 + tig];
            a[3] = Ps[r1 * 36 + kc * 8 + 4 + tig];
            const int row0 = kc * 8 + tig, row1 = row0 + 4;
            uint32_t vb0[16], vb1[16];
#pragma unroll
            for (int jq = 0; jq < 4; jq++) {
                *(uint4*)&vb0[jq * 4] = *(uint4*)&VsSt[row0 * 132 + g * 16 + jq * 4];
                *(uint4*)&vb1[jq * 4] = *(uint4*)&VsSt[row1 * 132 + g * 16 + jq * 4];
            }
#pragma unroll
            for (int j = 0; j < 16; j++)
                mma16h(oacc[j], a, vb0[j], vb1[j]);
        }
        __syncthreads();
    }

    // epilogue: write pre-split bf16 hi/lo tile-image directly
    float inv0 = 1.0f / l0, inv1 = 1.0f / l1;
#pragma unroll
    for (int j = 0; j < 16; j++) {
        int c = h * 128 + j * 8 + 2 * tig;
        float a0 = oacc[j][0] * inv0, a1 = oacc[j][1] * inv0;
        float b0v = oacc[j][2] * inv1, b1v = oacc[j][3] * inv1;
        size_t cb = (size_t)(q0 >> 7) * TILE_ELEMS + (size_t)(c >> 5) * SLAB_ELEMS
                  + (c & 31);
        size_t off0 = cb + r0 * 40;
        size_t off1 = cb + r1 * 40;
        *(uint32_t*)&oh[off0] = bfpack(a0, a1);
        *(uint32_t*)&ol[off0] = bfpack(bfres(a0), bfres(a1));
        *(uint32_t*)&oh[off1] = bfpack(b0v, b1v);
        *(uint32_t*)&ol[off1] = bfpack(bfres(b0v), bfres(b1v));
    }
}

// ---------------------------------------------------------------------------
extern "C" void kernel_launch(void* const* d_in, const int* in_sizes, int n_in,
                              void* d_out, int out_size)
{
    const float* x    = (const float*)d_in[0];
    const float* rope = (const float*)d_in[1];
    const float* Wq   = (const float*)d_in[2];
    const float* bq   = (const float*)d_in[3];
    const float* Wk   = (const float*)d_in[4];
    const float* bk   = (const float*)d_in[5];
    const float* Wv   = (const float*)d_in[6];
    const float* bv   = (const float*)d_in[7];
    const float* qn_w = (const float*)d_in[8];
    const float* kn_w = (const float*)d_in[9];
    const float* Wo   = (const float*)d_in[10];
    const float* bo   = (const float*)d_in[11];
    float* out = (float*)d_out;

    float* qp;
    uint32_t *khp, *klp, *vp;
    bf16 *xh, *xl, *ah, *al;
    bf16 *wqh, *wql, *wkh, *wkl, *wvh, *wvl, *woh, *wol;
    cudaGetSymbolAddress((void**)&qp,  g_q);
    cudaGetSymbolAddress((void**)&khp, g_kh);
    cudaGetSymbolAddress((void**)&klp, g_kl);
    cudaGetSymbolAddress((void**)&vp,  g_v);
    cudaGetSymbolAddress((void**)&xh,  g_xh);
    cudaGetSymbolAddress((void**)&xl,  g_xl);
    cudaGetSymbolAddress((void**)&ah,  g_ah);
    cudaGetSymbolAddress((void**)&al,  g_al);
    cudaGetSymbolAddress((void**)&wqh, g_wqh);
    cudaGetSymbolAddress((void**)&wql, g_wql);
    cudaGetSymbolAddress((void**)&wkh, g_wkh);
    cudaGetSymbolAddress((void**)&wkl, g_wkl);
    cudaGetSymbolAddress((void**)&wvh, g_wvh);
    cudaGetSymbolAddress((void**)&wvl, g_wvl);
    cudaGetSymbolAddress((void**)&woh, g_woh);
    cudaGetSymbolAddress((void**)&wol, g_wol);

    const int smem_gemm = 81920;
    const int smem_attn = 121856;
    cudaFuncSetAttribute(gemm_blk, cudaFuncAttributeMaxDynamicSharedMemorySize,
                         smem_gemm);
    cudaFuncSetAttribute(flash_attn_tc, cudaFuncAttributeMaxDynamicSharedMemorySize,
                         smem_attn);

    split_sw<<<8192, 256>>>(x,  xh,  xl);
    split_sw<<<4096, 256>>>(Wq, wqh, wql);
    split_sw<<<4096, 256>>>(Wk, wkh, wkl);
    split_sw<<<4096, 256>>>(Wv, wvh, wvl);
    split_sw<<<4096, 256>>>(Wo, woh, wol);

    dim3 ggrid(CC / 128, SS / 128);
    gemm_blk<<<ggrid, 256, smem_gemm>>>(xh, xl, wqh, wql, bq, qp, nullptr, nullptr,
                                        qn_w, rope, 1);
    gemm_blk<<<ggrid, 256, smem_gemm>>>(xh, xl, wkh, wkl, bk, nullptr, khp, klp,
                                        kn_w, rope, 2);
    gemm_blk<<<ggrid, 256, smem_gemm>>>(xh, xl, wvh, wvl, bv, nullptr, vp, nullptr,
                                        nullptr, nullptr, 3);

    dim3 agrid(SS / 128, HH);
    flash_attn_tc<<<agrid, 256, smem_attn>>>(qp, khp, klp, vp, ah, al);

    gemm_blk<<<ggrid, 256, smem_gemm>>>(ah, al, woh, wol, bo, out, nullptr, nullptr,
                                        nullptr, nullptr, 0);
}

// round 15
// speedup vs baseline: 5.1784x; 1.4573x over previous
#include <cuda_runtime.h>
#include <cstdint>
#include <cuda_bf16.h>
#include <cuda_fp16.h>
#include <mma.h>
#include <math.h>

using namespace nvcuda;

#define SS 4096
#define CC 2048
#define HH 16
#define DD 128
#define EPSF 1.1920929e-07f

// Scratch (no cudaMalloc allowed)
__device__ float    g_q[SS * CC];            // Q fp32 (post norm+rope)
__device__ uint32_t g_k[SS * HH * 64];       // K fp16 packed d-pairs (single)
__device__ uint32_t g_v[SS * HH * 64];       // V fp16 k-pair words [s/2][H][128]
// operands in PADDED TILE-IMAGE layout [tile=row/128][slab=k/32][128 x 40]
#define PADN(r, c) ((size_t)(r) * (c) * 5 / 4)
__device__ __half g_xh[PADN(SS, CC)], g_xl[PADN(SS, CC)];   // x fp16 hi/lo
__device__ __half g_ah[PADN(SS, CC)], g_al[PADN(SS, CC)];   // attn fp16 hi/lo
__device__ __half g_wq[PADN(CC, CC)];                        // weights single fp16
__device__ __half g_wk[PADN(CC, CC)];
__device__ __half g_wv[PADN(CC, CC)];
__device__ __half g_wo[PADN(CC, CC)];

#define TILE_ELEMS 327680u    // 64 slabs * 5120 elems
#define SLAB_ELEMS 5120u      // 128 rows * 40 halves

// ---------------------------------------------------------------------------
// helpers
// ---------------------------------------------------------------------------
__device__ __forceinline__ uint32_t h2pack(float x, float y) {
    __half2 h = __floats2half2_rn(x, y);
    return *(uint32_t*)&h;
}
__device__ __forceinline__ float hres(float x) {
    return x - __half2float(__float2half_rn(x));
}

// fp16 m16n8k16
__device__ __forceinline__ void mma16h(float* c, const uint32_t* a,
                                       uint32_t b0, uint32_t b1) {
    asm volatile(
        "mma.sync.aligned.m16n8k16.row.col.f32.f16.f16.f32 "
        "{%0,%1,%2,%3}, {%4,%5,%6,%7}, {%8,%9}, {%0,%1,%2,%3};\n"
        : "+f"(c[0]), "+f"(c[1]), "+f"(c[2]), "+f"(c[3])
        : "r"(a[0]), "r"(a[1]), "r"(a[2]), "r"(a[3]), "r"(b0), "r"(b1));
}

#define CP16(dst_u32, src_ptr) \
    asm volatile("cp.async.cg.shared.global [%0], [%1], 16;" \
                 :: "r"(dst_u32), "l"(src_ptr) : "memory")
#define CP_COMMIT() asm volatile("cp.async.commit_group;" ::: "memory")

__device__ __forceinline__ void ldsm_x4(uint32_t addr, uint32_t& r0, uint32_t& r1,
                                        uint32_t& r2, uint32_t& r3) {
    asm volatile("ldmatrix.sync.aligned.m8n8.x4.shared.b16 {%0,%1,%2,%3}, [%4];"
                 : "=r"(r0), "=r"(r1), "=r"(r2), "=r"(r3) : "r"(addr));
}

__device__ __forceinline__ uint32_t smem_u32(const void* p) {
    uint32_t a;
    asm("{ .reg .u64 tt; cvta.to.shared.u64 tt, %1; cvt.u32.u64 %0, tt; }"
        : "=r"(a) : "l"(p));
    return a;
}

// --- mbarrier + bulk-DMA primitives ---
#define MBINIT(m, c) \
    asm volatile("mbarrier.init.shared.b64 [%0], %1;" :: "r"(m), "r"(c) : "memory")
#define MBEXPECT(m, b) \
    asm volatile("mbarrier.arrive.expect_tx.shared.b64 _, [%0], %1;" :: "r"(m), "r"(b) : "memory")
#define BULKCP(dst, src, bytes, mbar) \
    asm volatile("cp.async.bulk.shared::cta.global.mbarrier::complete_tx::bytes [%0], [%1], %2, [%3];" \
                 :: "r"(dst), "l"(src), "r"(bytes), "r"(mbar) : "memory")

#define MBWAIT(mbar_addr, parity) do { \
    uint32_t _m = (mbar_addr), _p = (parity), _d; \
    asm volatile( \
        "{\n\t.reg .pred p;\n\t" \
        "mbarrier.try_wait.parity.acquire.cta.shared::cta.b64 p, [%1], %2;\n\t" \
        "selp.b32 %0, 1, 0, p;\n\t}" \
        : "=r"(_d) : "r"(_m), "r"(_p) : "memory"); \
    if (!_d) { \
        asm volatile( \
            "{\n\t.reg .pred P1;\n\t" \
            "WL_%=:\n\t" \
            "mbarrier.try_wait.parity.acquire.cta.shared::cta.b64 P1, [%0], %1, 0x989680;\n\t" \
            "@P1 bra.uni WD_%=;\n\t" \
            "bra.uni WL_%=;\n\t" \
            "WD_%=:\n\t}" \
            :: "r"(_m), "r"(_p) : "memory"); \
    } \
} while (0)

// ---------------------------------------------------------------------------
// splits: fp32 -> fp16 hi(+lo) in padded tile-image layout
// ---------------------------------------------------------------------------
__global__ void split_a16(const float* __restrict__ in,
                          __half* __restrict__ oh, __half* __restrict__ ol)
{
    int idx = blockIdx.x * 256 + threadIdx.x;
    int r  = idx >> 9;
    int kc = (idx & 511) * 4;
    float4 v = *(const float4*)&in[(size_t)r * 2048 + kc];
    uint2 h = make_uint2(h2pack(v.x, v.y), h2pack(v.z, v.w));
    uint2 l = make_uint2(h2pack(hres(v.x), hres(v.y)),
                         h2pack(hres(v.z), hres(v.w)));
    size_t off = (size_t)(r >> 7) * TILE_ELEMS + (size_t)(kc >> 5) * SLAB_ELEMS
               + (r & 127) * 40 + (kc & 31);
    *(uint2*)&oh[off] = h;
    *(uint2*)&ol[off] = l;
}

__global__ void split_w16(const float* __restrict__ in, __half* __restrict__ oh)
{
    int idx = blockIdx.x * 256 + threadIdx.x;
    int r  = idx >> 9;
    int kc = (idx & 511) * 4;
    float4 v = *(const float4*)&in[(size_t)r * 2048 + kc];
    uint2 h = make_uint2(h2pack(v.x, v.y), h2pack(v.z, v.w));
    size_t off = (size_t)(r >> 7) * TILE_ELEMS + (size_t)(kc >> 5) * SLAB_ELEMS
               + (r & 127) * 40 + (kc & 31);
    *(uint2*)&oh[off] = h;
}

// ---------------------------------------------------------------------------
// GEMM: Out = A @ B^T + bias. A fp16 hi/lo (2-term), B single fp16.
// bulk-DMA 2-stage pipeline; wmma fp16 m16n16k16; 128x128x32 tile, 256 thr.
// stage (bytes): Ah +0, Al +10240, Bh +20480  -> 30720/stage
// mode 0: fp32 out  1: norm+rope fp32 (Q)  2: norm+rope fp16 K pairs
// mode 3: fp16 V pairs
// ---------------------------------------------------------------------------
__global__ void __launch_bounds__(256, 2)
gemm_blk(const __half* __restrict__ Ahg, const __half* __restrict__ Alg,
         const __half* __restrict__ Bhg,
         const float* __restrict__ bias,
         float* __restrict__ Out,
         uint32_t* __restrict__ outW1,
         const float* __restrict__ normw, const float* __restrict__ rope,
         int mode)
{
    extern __shared__ char smemc[];
    __shared__ uint64_t s_mbar[2];

    const uint32_t sbase = smem_u32(smemc);
    const uint32_t mb0 = smem_u32(&s_mbar[0]);
    const uint32_t mb1 = smem_u32(&s_mbar[1]);

    const int t = threadIdx.x;
    const int warp = t >> 5;
    const int wr = warp >> 2;
    const int wc = warp & 3;
    const int m0 = blockIdx.y * 128;
    const int n0 = blockIdx.x * 128;
    const int hh = blockIdx.x;

    if (t == 0) { MBINIT(mb0, 1); MBINIT(mb1, 1); }
    __syncthreads();

    const __half* pAh = Ahg + (size_t)(m0 >> 7) * TILE_ELEMS;
    const __half* pAl = Alg + (size_t)(m0 >> 7) * TILE_ELEMS;
    const __half* pBh = Bhg + (size_t)(n0 >> 7) * TILE_ELEMS;

    auto fill = [&](int s) {
        int st = s & 1;
        uint32_t fb = st ? mb1 : mb0;
        uint32_t d  = sbase + st * 30720;
        size_t o = (size_t)s * SLAB_ELEMS;
        MBEXPECT(fb, 30720u);
        BULKCP(d,         pAh + o, 10240u, fb);
        BULKCP(d + 10240, pAl + o, 10240u, fb);
        BULKCP(d + 20480, pBh + o, 10240u, fb);
    };

    if (t == 0) { fill(0); fill(1); }

    wmma::fragment<wmma::accumulator, 16, 16, 16, float> cfrag[4][2];
#pragma unroll
    for (int mi = 0; mi < 4; mi++)
#pragma unroll
        for (int nj = 0; nj < 2; nj++) wmma::fill_fragment(cfrag[mi][nj], 0.0f);

    for (int s = 0; s < 64; s++) {
        const int st = s & 1;
        const uint32_t ph = (uint32_t)((s >> 1) & 1);
        MBWAIT(st ? mb1 : mb0, ph);

        __half* Ash = (__half*)(smemc + st * 30720);
        __half* Asl = Ash + 5120;
        __half* Bsh = Ash + 10240;

#pragma unroll
        for (int ks = 0; ks < 2; ks++) {
            wmma::fragment<wmma::matrix_b, 16, 16, 16, half, wmma::col_major> bh[2];
#pragma unroll
            for (int nj = 0; nj < 2; nj++)
                wmma::load_matrix_sync(bh[nj], &Bsh[(wc * 32 + nj * 16) * 40 + ks * 16], 40);
#pragma unroll
            for (int mi = 0; mi < 4; mi++) {
                wmma::fragment<wmma::matrix_a, 16, 16, 16, half, wmma::row_major> ah, al;
                wmma::load_matrix_sync(ah, &Ash[(wr * 64 + mi * 16) * 40 + ks * 16], 40);
                wmma::load_matrix_sync(al, &Asl[(wr * 64 + mi * 16) * 40 + ks * 16], 40);
#pragma unroll
                for (int nj = 0; nj < 2; nj++) {
                    wmma::mma_sync(cfrag[mi][nj], al, bh[nj], cfrag[mi][nj]);
                    wmma::mma_sync(cfrag[mi][nj], ah, bh[nj], cfrag[mi][nj]);
                }
            }
        }
        __syncthreads();
        if (t == 0 && s + 2 < 64) fill(s + 2);
    }

    float* Cs = (float*)smemc;  // [128][132] = 67584 B
#pragma unroll
    for (int mi = 0; mi < 4; mi++)
#pragma unroll
        for (int nj = 0; nj < 2; nj++)
            wmma::store_matrix_sync(&Cs[(wr * 64 + mi * 16) * 132 + wc * 32 + nj * 16],
                                    cfrag[mi][nj], 132, wmma::mem_row_major);
    __syncthreads();

    if (mode == 0) {
#pragma unroll
        for (int i = 0; i < 16; i++) {
            int idx = i * 256 + t;
            int r = idx >> 5, c4 = (idx & 31) * 4;
            float4 cv = *(float4*)&Cs[r * 132 + c4];
            float4 bb = *(const float4*)&bias[n0 + c4];
            cv.x += bb.x; cv.y += bb.y; cv.z += bb.z; cv.w += bb.w;
            *(float4*)&Out[(size_t)(m0 + r) * CC + n0 + c4] = cv;
        }
    } else if (mode == 3) {
        // V: fp16 halves packed as k-pairs (s even -> low half); d interleaved
        __half* vh = (__half*)outW1;
#pragma unroll
        for (int i = 0; i < 16; i++) {
            int idx = i * 256 + t;
            int r = idx >> 5, c4 = (idx & 31) * 4;
            float4 cv = *(float4*)&Cs[r * 132 + c4];
            float4 bb = *(const float4*)&bias[n0 + c4];
            cv.x += bb.x; cv.y += bb.y; cv.z += bb.z; cv.w += bb.w;
            int sidx = m0 + r;
            size_t wb = ((size_t)(sidx >> 1) * HH + hh) * 128;
            float vals[4] = {cv.x, cv.y, cv.z, cv.w};
#pragma unroll
            for (int e = 0; e < 4; e++) {
                int d = c4 + e;
                int dp = (d & 7) * 16 + (d >> 3);
                vh[(wb + dp) * 2 + (sidx & 1)] = __float2half_rn(vals[e]);
            }
        }
    } else {
        const int r = t >> 1, half_ = t & 1;
        const int s = m0 + r;
        float* row = &Cs[r * 132 + half_ * 64];
        const float* bias_h = &bias[n0 + half_ * 64];
        float ssq = 0.0f;
#pragma unroll
        for (int j = 0; j < 16; j++) {
            float4 c = ((float4*)row)[j];
            float4 bb = ((const float4*)bias_h)[j];
            c.x += bb.x; c.y += bb.y; c.z += bb.z; c.w += bb.w;
            ((float4*)row)[j] = c;
            ssq += c.x * c.x + c.y * c.y + c.z * c.z + c.w * c.w;
        }
        ssq += __shfl_xor_sync(0xffffffffu, ssq, 1);
        float inv = rsqrtf(ssq * (1.0f / 128.0f) + EPSF);
        const float* wv = &normw[half_ * 64];
        const float* rp = &rope[(size_t)s * 256 + half_ * 128];
        float* outp = &Out[(size_t)(m0 + r) * CC + n0 + half_ * 64];
#pragma unroll
        for (int j = 0; j < 16; j++) {
            float4 c = ((float4*)row)[j];
            float4 ww = ((const float4*)wv)[j];
            float x0 = c.x * inv * ww.x;
            float x1 = c.y * inv * ww.y;
            float x2 = c.z * inv * ww.z;
            float x3 = c.w * inv * ww.w;
            float4 rA = ((const float4*)rp)[2 * j];
            float4 rB = ((const float4*)rp)[2 * j + 1];
            float4 ov;
            ov.x = rA.x * x0 + rA.y * x1;
            ov.y = rA.z * x0 + rA.w * x1;
            ov.z = rB.x * x2 + rB.y * x3;
            ov.w = rB.z * x2 + rB.w * x3;
            if (mode == 1) {
                ((float4*)outp)[j] = ov;
            } else {
                // mode 2: K single fp16 packed d-pairs
                size_t kb = ((size_t)s * HH + hh) * 64 + half_ * 32 + j * 2;
                uint2 w = make_uint2(h2pack(ov.x, ov.y), h2pack(ov.z, ov.w));
                *(uint2*)&outW1[kb] = w;
            }
        }
    }
}

// ---------------------------------------------------------------------------
// Flash attention: QK fp16 2-term (Q hi/lo regs, K single fp16 ldmatrix),
// PV fp16; output written as pre-split fp16 hi/lo tile-image.
// smem words: KsH st*4352 [64][68]; Vs 8704+st*4224 [32][132]; Ps 17152 [128][36].
// Total 21760 w = 87040 B.
// ---------------------------------------------------------------------------
__global__ void __launch_bounds__(256, 1)
flash_attn_tc(const float* __restrict__ q,
              const uint32_t* __restrict__ kk,
              const uint32_t* __restrict__ vv,
              __half* __restrict__ oh, __half* __restrict__ ol)
{
    extern __shared__ uint32_t usm[];
    uint32_t sbase = smem_u32(usm);

    const int h  = blockIdx.y;
    const int q0 = blockIdx.x * 128;
    const int t  = threadIdx.x;
    const int warp = t >> 5;
    const int lane = t & 31;
    const int g   = lane >> 2;
    const int tig = lane & 3;
    const int r0 = warp * 16 + g;
    const int r1 = r0 + 8;
    const float scale = 0.08838834764831845f;

    uint32_t* Ps = usm + 17152;

    const int rowsel = (lane & 7) + ((lane >> 4) & 1) * 8;
    const int halfw  = ((lane >> 3) & 1) * 4;

    // Q -> fp16 hi + residual lo in registers (pre-scaled)
    uint32_t qh[8][4], ql[8][4];
    {
        const float* qr0 = &q[((size_t)(q0 + r0) * HH + h) * DD];
        const float* qr1 = &q[((size_t)(q0 + r1) * HH + h) * DD];
#pragma unroll
        for (int ks = 0; ks < 8; ks++) {
            int c = ks * 16 + 2 * tig;
            float a0 = qr0[c] * scale,     a1 = qr0[c + 1] * scale;
            float b0 = qr1[c] * scale,     b1 = qr1[c + 1] * scale;
            float c0 = qr0[c + 8] * scale, c1 = qr0[c + 9] * scale;
            float d0 = qr1[c + 8] * scale, d1 = qr1[c + 9] * scale;
            qh[ks][0] = h2pack(a0, a1);
            qh[ks][1] = h2pack(b0, b1);
            qh[ks][2] = h2pack(c0, c1);
            qh[ks][3] = h2pack(d0, d1);
            ql[ks][0] = h2pack(hres(a0), hres(a1));
            ql[ks][1] = h2pack(hres(b0), hres(b1));
            ql[ks][2] = h2pack(hres(c0), hres(c1));
            ql[ks][3] = h2pack(hres(d0), hres(d1));
        }
    }

    float m0r = -1e30f, m1r = -1e30f, l0 = 0.0f, l1 = 0.0f;
    float oacc[16][4];
#pragma unroll
    for (int j = 0; j < 16; j++)
#pragma unroll
        for (int e = 0; e < 4; e++) oacc[j][e] = 0.0f;

    auto fill = [&](int st, int kv) {
        const uint32_t dKH = sbase + (st * 4352) * 4;
        const uint32_t dV  = sbase + (8704 + st * 4224) * 4;
#pragma unroll
        for (int i = 0; i < 4; i++) {
            int c = i * 256 + t; int r = c >> 4, w = (c & 15) * 4;
            CP16(dKH + (uint32_t)(r * 68 + w) * 4,
                 &kk[((size_t)(kv + r) * HH + h) * 64 + w]);
        }
#pragma unroll
        for (int i = 0; i < 4; i++) {
            int c = i * 256 + t; int pr = c >> 5, w = (c & 31) * 4;
            CP16(dV + (uint32_t)(pr * 132 + w) * 4,
                 &vv[((size_t)((kv >> 1) + pr) * HH + h) * 128 + w]);
        }
    };

    fill(0, 0);
    CP_COMMIT();

    for (int kv0 = 0; kv0 < SS; kv0 += 64) {
        const int st = (kv0 >> 6) & 1;
        const bool more = (kv0 + 64) < SS;

        if (more) { fill(st ^ 1, kv0 + 64); CP_COMMIT(); }

        if (more) { asm volatile("cp.async.wait_group 1;" ::: "memory"); }
        else      { asm volatile("cp.async.wait_group 0;" ::: "memory"); }
        __syncthreads();

        const uint32_t bKH = sbase + (st * 4352) * 4;
        uint32_t* VsSt = usm + 8704 + st * 4224;

        float sacc[8][4];
#pragma unroll
        for (int j = 0; j < 8; j++)
#pragma unroll
            for (int e = 0; e < 4; e++) sacc[j][e] = 0.0f;

#pragma unroll
        for (int ks = 0; ks < 8; ks++) {
#pragma unroll
            for (int jp = 0; jp < 4; jp++) {
                uint32_t woff = (uint32_t)((jp * 16 + rowsel) * 68 + ks * 8 + halfw) * 4;
                uint32_t h0, h1, h2, h3;
                ldsm_x4(bKH + woff, h0, h1, h2, h3);
                mma16h(sacc[2 * jp],     ql[ks], h0, h1);
                mma16h(sacc[2 * jp],     qh[ks], h0, h1);
                mma16h(sacc[2 * jp + 1], ql[ks], h2, h3);
                mma16h(sacc[2 * jp + 1], qh[ks], h2, h3);
            }
        }

        float rmax0 = -1e30f, rmax1 = -1e30f;
#pragma unroll
        for (int j = 0; j < 8; j++) {
            rmax0 = fmaxf(rmax0, fmaxf(sacc[j][0], sacc[j][1]));
            rmax1 = fmaxf(rmax1, fmaxf(sacc[j][2], sacc[j][3]));
        }
#pragma unroll
        for (int off = 1; off < 4; off <<= 1) {
            rmax0 = fmaxf(rmax0, __shfl_xor_sync(0xffffffffu, rmax0, off));
            rmax1 = fmaxf(rmax1, __shfl_xor_sync(0xffffffffu, rmax1, off));
        }
        float mn0 = fmaxf(m0r, rmax0);
        float mn1 = fmaxf(m1r, rmax1);
        float cr0 = __expf(m0r - mn0);
        float cr1 = __expf(m1r - mn1);
        float rs0 = 0.0f, rs1 = 0.0f;
#pragma unroll
        for (int j = 0; j < 8; j++) {
            float e0 = __expf(sacc[j][0] - mn0);
            float e1 = __expf(sacc[j][1] - mn0);
            float e2 = __expf(sacc[j][2] - mn1);
            float e3 = __expf(sacc[j][3] - mn1);
            rs0 += e0 + e1;
            rs1 += e2 + e3;
            int wcol = j * 4 + tig;
            Ps[r0 * 36 + wcol] = h2pack(e0, e1);
            Ps[r1 * 36 + wcol] = h2pack(e2, e3);
        }
#pragma unroll
        for (int off = 1; off < 4; off <<= 1) {
            rs0 += __shfl_xor_sync(0xffffffffu, rs0, off);
            rs1 += __shfl_xor_sync(0xffffffffu, rs1, off);
        }
        l0 = l0 * cr0 + rs0;
        l1 = l1 * cr1 + rs1;
        m0r = mn0;
        m1r = mn1;
#pragma unroll
        for (int j = 0; j < 16; j++) {
            oacc[j][0] *= cr0; oacc[j][1] *= cr0;
            oacc[j][2] *= cr1; oacc[j][3] *= cr1;
        }
        __syncwarp();

        // ---- PV: fp16 m16n8k16, k=64 -> 4 k-steps ----
#pragma unroll
        for (int kc = 0; kc < 4; kc++) {
            uint32_t a[4];
            a[0] = Ps[r0 * 36 + kc * 8 + tig];
            a[1] = Ps[r1 * 36 + kc * 8 + tig];
            a[2] = Ps[r0 * 36 + kc * 8 + 4 + tig];
            a[3] = Ps[r1 * 36 + kc * 8 + 4 + tig];
            const int row0 = kc * 8 + tig, row1 = row0 + 4;
            uint32_t vb0[16], vb1[16];
#pragma unroll
            for (int jq = 0; jq < 4; jq++) {
                *(uint4*)&vb0[jq * 4] = *(uint4*)&VsSt[row0 * 132 + g * 16 + jq * 4];
                *(uint4*)&vb1[jq * 4] = *(uint4*)&VsSt[row1 * 132 + g * 16 + jq * 4];
            }
#pragma unroll
            for (int j = 0; j < 16; j++)
                mma16h(oacc[j], a, vb0[j], vb1[j]);
        }
        __syncthreads();
    }

    // epilogue: write pre-split fp16 hi/lo tile-image directly
    float inv0 = 1.0f / l0, inv1 = 1.0f / l1;
#pragma unroll
    for (int j = 0; j < 16; j++) {
        int c = h * 128 + j * 8 + 2 * tig;
        float a0 = oacc[j][0] * inv0, a1 = oacc[j][1] * inv0;
        float b0v = oacc[j][2] * inv1, b1v = oacc[j][3] * inv1;
        size_t cb = (size_t)(q0 >> 7) * TILE_ELEMS + (size_t)(c >> 5) * SLAB_ELEMS
                  + (c & 31);
        size_t off0 = cb + r0 * 40;
        size_t off1 = cb + r1 * 40;
        *(uint32_t*)&oh[off0] = h2pack(a0, a1);
        *(uint32_t*)&ol[off0] = h2pack(hres(a0), hres(a1));
        *(uint32_t*)&oh[off1] = h2pack(b0v, b1v);
        *(uint32_t*)&ol[off1] = h2pack(hres(b0v), hres(b1v));
    }
}

// ---------------------------------------------------------------------------
extern "C" void kernel_launch(void* const* d_in, const int* in_sizes, int n_in,
                              void* d_out, int out_size)
{
    const float* x    = (const float*)d_in[0];
    const float* rope = (const float*)d_in[1];
    const float* Wq   = (const float*)d_in[2];
    const float* bq   = (const float*)d_in[3];
    const float* Wk   = (const float*)d_in[4];
    const float* bk   = (const float*)d_in[5];
    const float* Wv   = (const float*)d_in[6];
    const float* bv   = (const float*)d_in[7];
    const float* qn_w = (const float*)d_in[8];
    const float* kn_w = (const float*)d_in[9];
    const float* Wo   = (const float*)d_in[10];
    const float* bo   = (const float*)d_in[11];
    float* out = (float*)d_out;

    float* qp;
    uint32_t *kp, *vp;
    __half *xh, *xl, *ah, *al, *wq, *wk, *wv, *wo;
    cudaGetSymbolAddress((void**)&qp, g_q);
    cudaGetSymbolAddress((void**)&kp, g_k);
    cudaGetSymbolAddress((void**)&vp, g_v);
    cudaGetSymbolAddress((void**)&xh, g_xh);
    cudaGetSymbolAddress((void**)&xl, g_xl);
    cudaGetSymbolAddress((void**)&ah, g_ah);
    cudaGetSymbolAddress((void**)&al, g_al);
    cudaGetSymbolAddress((void**)&wq, g_wq);
    cudaGetSymbolAddress((void**)&wk, g_wk);
    cudaGetSymbolAddress((void**)&wv, g_wv);
    cudaGetSymbolAddress((void**)&wo, g_wo);

    const int smem_gemm = 67584;   // max(2*30720 stages, Cs 128*132*4)
    const int smem_attn = 87040;
    cudaFuncSetAttribute(gemm_blk, cudaFuncAttributeMaxDynamicSharedMemorySize,
                         smem_gemm);
    cudaFuncSetAttribute(flash_attn_tc, cudaFuncAttributeMaxDynamicSharedMemorySize,
                         smem_attn);

    split_a16<<<8192, 256>>>(x, xh, xl);
    split_w16<<<4096, 256>>>(Wq, wq);
    split_w16<<<4096, 256>>>(Wk, wk);
    split_w16<<<4096, 256>>>(Wv, wv);
    split_w16<<<4096, 256>>>(Wo, wo);

    dim3 ggrid(CC / 128, SS / 128);
    gemm_blk<<<ggrid, 256, smem_gemm>>>(xh, xl, wq, bq, qp, nullptr, qn_w, rope, 1);
    gemm_blk<<<ggrid, 256, smem_gemm>>>(xh, xl, wk, bk, nullptr, kp, kn_w, rope, 2);
    gemm_blk<<<ggrid, 256, smem_gemm>>>(xh, xl, wv, bv, nullptr, vp, nullptr, nullptr, 3);

    dim3 agrid(SS / 128, HH);
    flash_attn_tc<<<agrid, 256, smem_attn>>>(qp, kp, vp, ah, al);

    gemm_blk<<<ggrid, 256, smem_gemm>>>(ah, al, wo, bo, out, nullptr, nullptr, nullptr, 0);
}